// round 13
// baseline (speedup 1.0000x reference)
#include <cuda_runtime.h>
#include <math.h>
#include <stdint.h>

// Problem constants
#define TT 2048
#define BB 2
#define EE 1024
#define HH 8
#define DD 128
#define RR 2
#define CHUNKC 32
#define CC (TT/CHUNKC)   // 64
#define KTOT 1024
#define NTOT 1024

typedef unsigned long long u64;

// packed f32x2 helpers (sm_100+ PTX; ptxas never auto-fuses these)
#define FMA2(acc, x, y) \
    asm("fma.rn.f32x2 %0, %1, %2, %0;" : "+l"(acc) : "l"(x), "l"(y))
#define SPLAT2(d, s) \
    asm("mov.b64 %0, {%1, %1};" : "=l"(d) : "r"(s))

__device__ __forceinline__ float lo_f(u64 v) { return __uint_as_float((uint32_t)v); }
__device__ __forceinline__ float hi_f(u64 v) { return __uint_as_float((uint32_t)(v >> 32)); }

__device__ __forceinline__ uint32_t smem_u32(const void* p) {
    uint32_t a;
    asm("{ .reg .u64 t; cvta.to.shared.u64 t, %1; cvt.u32.u64 %0, t; }" : "=r"(a) : "l"(p));
    return a;
}
__device__ __forceinline__ void cp_async16(uint32_t smem_addr, const void* gptr) {
    asm volatile("cp.async.ca.shared.global [%0], [%1], 16;" :: "r"(smem_addr), "l"(gptr));
}
#define CP_COMMIT() asm volatile("cp.async.commit_group;" ::: "memory")
#define CP_WAIT0()  asm volatile("cp.async.wait_group 0;" ::: "memory")

// -------------------- device scratch --------------------
__device__ float g_qf[TT*BB*EE];
__device__ float g_vf[TT*BB*EE];
__device__ float g_invnorm[TT*BB];
__device__ int   g_hash[BB*RR*HH*TT];
__device__ int   g_perm[BB*RR*HH*TT];
__device__ int   g_inv [BB*RR*HH*TT];
__device__ float g_o[RR*BB*HH*TT*DD];
__device__ float g_z[RR*BB*HH*TT];

// ==================== exact-fp32 SGEMM (f32x2 + cp.async B): out = A @ W + bias ====================
#define KS 16
#define NST (KTOT/KS)   // 64

__global__ void __launch_bounds__(256, 2) sgemm_kernel(
    const float* __restrict__ A0, const float* __restrict__ W0,
    const float* __restrict__ b0, float* __restrict__ o0,
    const float* __restrict__ A1, const float* __restrict__ W1,
    const float* __restrict__ b1, float* __restrict__ o1)
{
    const float* A    = blockIdx.z ? A1 : A0;
    const float* W    = blockIdx.z ? W1 : W0;
    const float* bias = blockIdx.z ? b1 : b0;
    float*       out  = blockIdx.z ? o1 : o0;

    __shared__ __align__(16) float As[2][KS][132];
    __shared__ __align__(16) float Bs[2][KS][128];
    __shared__ float bsm[128];

    const int tid = threadIdx.x;
    const int bm = blockIdx.y * 128;
    const int bn = blockIdx.x * 128;
    const int tx = tid & 15;
    const int ty = tid >> 4;

    if (tid < 128) bsm[tid] = bias[bn + tid];

    const int arow = tid >> 2;
    const int akq  = tid & 3;
    const int bkr = tid >> 5;
    const int bn4 = tid & 31;

    const float* Ap0 = A + (size_t)(bm + arow) * KTOT + akq * 4;
    const float* Ap1 = A + (size_t)(bm + 64 + arow) * KTOT + akq * 4;
    const float* Wp0 = W + (size_t)bkr * NTOT + bn + bn4 * 4;
    const float* Wp1 = W + (size_t)(8 + bkr) * NTOT + bn + bn4 * 4;

    const uint32_t bs_a0 = smem_u32(&Bs[0][bkr][bn4*4]);
    const uint32_t bs_a1 = smem_u32(&Bs[0][8+bkr][bn4*4]);
    const uint32_t bs_b0 = smem_u32(&Bs[1][bkr][bn4*4]);
    const uint32_t bs_b1 = smem_u32(&Bs[1][8+bkr][bn4*4]);

    float4 pa0, pa1;
    u64 acc2[4][8];
    #pragma unroll
    for (int i = 0; i < 4; i++)
        #pragma unroll
        for (int j = 0; j < 8; j++) acc2[i][j] = 0ull;

    pa0 = *(const float4*)(Ap0);
    pa1 = *(const float4*)(Ap1);
    cp_async16(bs_a0, Wp0);
    cp_async16(bs_a1, Wp1);
    CP_COMMIT();
    {
        const int kb = akq * 4;
        As[0][kb+0][arow]    = pa0.x; As[0][kb+1][arow]    = pa0.y;
        As[0][kb+2][arow]    = pa0.z; As[0][kb+3][arow]    = pa0.w;
        As[0][kb+0][64+arow] = pa1.x; As[0][kb+1][64+arow] = pa1.y;
        As[0][kb+2][64+arow] = pa1.z; As[0][kb+3][64+arow] = pa1.w;
    }
    CP_WAIT0();
    __syncthreads();

    for (int s = 0; s < NST; s++) {
        const int buf = s & 1;
        if (s + 1 < NST) {
            const size_t ko = (size_t)(s + 1) * KS;
            pa0 = *(const float4*)(Ap0 + ko);
            pa1 = *(const float4*)(Ap1 + ko);
            cp_async16(buf ? bs_a0 : bs_b0, Wp0 + ko * NTOT);
            cp_async16(buf ? bs_a1 : bs_b1, Wp1 + ko * NTOT);
            CP_COMMIT();
        }
        #pragma unroll
        for (int k = 0; k < KS; k++) {
            ulonglong2 a0 = *(const ulonglong2*)&As[buf][k][ty*4];
            ulonglong2 a1 = *(const ulonglong2*)&As[buf][k][64 + ty*4];
            float4 bv0 = *(const float4*)&Bs[buf][k][tx*4];
            float4 bv1 = *(const float4*)&Bs[buf][k][64 + tx*4];
            u64 ap[4] = {a0.x, a0.y, a1.x, a1.y};
            u64 bs2[8];
            SPLAT2(bs2[0], __float_as_uint(bv0.x));
            SPLAT2(bs2[1], __float_as_uint(bv0.y));
            SPLAT2(bs2[2], __float_as_uint(bv0.z));
            SPLAT2(bs2[3], __float_as_uint(bv0.w));
            SPLAT2(bs2[4], __float_as_uint(bv1.x));
            SPLAT2(bs2[5], __float_as_uint(bv1.y));
            SPLAT2(bs2[6], __float_as_uint(bv1.z));
            SPLAT2(bs2[7], __float_as_uint(bv1.w));
            #pragma unroll
            for (int i = 0; i < 4; i++)
                #pragma unroll
                for (int j = 0; j < 8; j++)
                    FMA2(acc2[i][j], ap[i], bs2[j]);
        }
        if (s + 1 < NST) {
            const int nb = buf ^ 1;
            __syncthreads();
            const int kb = akq * 4;
            As[nb][kb+0][arow]    = pa0.x; As[nb][kb+1][arow]    = pa0.y;
            As[nb][kb+2][arow]    = pa0.z; As[nb][kb+3][arow]    = pa0.w;
            As[nb][kb+0][64+arow] = pa1.x; As[nb][kb+1][64+arow] = pa1.y;
            As[nb][kb+2][64+arow] = pa1.z; As[nb][kb+3][64+arow] = pa1.w;
            CP_WAIT0();
            __syncthreads();
        }
    }

    #pragma unroll
    for (int i2 = 0; i2 < 4; i2++) {
        const int mrow = bm + ((i2 < 2) ? (ty*4 + i2*2) : (64 + ty*4 + (i2-2)*2));
        const int n0 = tx*4, n1 = 64 + tx*4;
        float* r0 = out + (size_t)mrow * NTOT + bn;
        float* r1 = out + (size_t)(mrow+1) * NTOT + bn;
        float4 lo0, lo1, hi0, hi1;
        lo0.x = lo_f(acc2[i2][0]) + bsm[n0+0]; hi0.x = hi_f(acc2[i2][0]) + bsm[n0+0];
        lo0.y = lo_f(acc2[i2][1]) + bsm[n0+1]; hi0.y = hi_f(acc2[i2][1]) + bsm[n0+1];
        lo0.z = lo_f(acc2[i2][2]) + bsm[n0+2]; hi0.z = hi_f(acc2[i2][2]) + bsm[n0+2];
        lo0.w = lo_f(acc2[i2][3]) + bsm[n0+3]; hi0.w = hi_f(acc2[i2][3]) + bsm[n0+3];
        lo1.x = lo_f(acc2[i2][4]) + bsm[n1+0]; hi1.x = hi_f(acc2[i2][4]) + bsm[n1+0];
        lo1.y = lo_f(acc2[i2][5]) + bsm[n1+1]; hi1.y = hi_f(acc2[i2][5]) + bsm[n1+1];
        lo1.z = lo_f(acc2[i2][6]) + bsm[n1+2]; hi1.z = hi_f(acc2[i2][6]) + bsm[n1+2];
        lo1.w = lo_f(acc2[i2][7]) + bsm[n1+3]; hi1.w = hi_f(acc2[i2][7]) + bsm[n1+3];
        *(float4*)(r0 + n0) = lo0;
        *(float4*)(r0 + n1) = lo1;
        *(float4*)(r1 + n0) = hi0;
        *(float4*)(r1 + n1) = hi1;
    }
}

// ==================== Wo SGEMM with fused round-combine A-path ====================
// A[m][k] = w0(b,h,t)*o_r0 + w1*o_r1, m = tb = t*BB+b, h = k>>7 (constant per K-stage).
__global__ void __launch_bounds__(256, 2) sgemm_wo_kernel(
    const float* __restrict__ W, const float* __restrict__ bias,
    float* __restrict__ out)
{
    __shared__ __align__(16) float As[2][KS][132];
    __shared__ __align__(16) float Bs[2][KS][128];
    __shared__ float bsm[128];
    __shared__ float2 wsm[128][8];   // [row in tile][h] -> (w0, w1)

    const int tid = threadIdx.x;
    const int bm = blockIdx.y * 128;
    const int bn = blockIdx.x * 128;
    const int tx = tid & 15;
    const int ty = tid >> 4;

    if (tid < 128) bsm[tid] = bias[bn + tid];

    // build combine-weight table: 1024 entries, 4 per thread
    #pragma unroll
    for (int i = 0; i < 4; i++) {
        int idx = tid + i*256;
        int row = idx >> 3, h = idx & 7;
        int tb = bm + row, t = tb >> 1, b = tb & 1;
        int zi = (b*HH + h)*TT + t;
        float z0 = g_z[zi];
        float z1 = g_z[BB*HH*TT + zi];
        float mz = fmaxf(z0, z1);
        float e0 = __expf(z0 - mz), e1 = __expf(z1 - mz);
        float winv = 1.0f / (e0 + e1);
        wsm[row][h] = make_float2(e0*winv, e1*winv);
    }

    const int arow = tid >> 2;
    const int akq  = tid & 3;
    const int bkr = tid >> 5;
    const int bn4 = tid & 31;

    // o-row base offsets for this thread's two tile rows (sans h, d)
    int tb0 = bm + arow,      t0 = tb0 >> 1, b0 = tb0 & 1;
    int tb1 = bm + 64 + arow, t1 = tb1 >> 1, b1 = tb1 & 1;
    const size_t ob0 = (size_t)b0*HH*TT*DD + (size_t)t0*DD;
    const size_t ob1 = (size_t)b1*HH*TT*DD + (size_t)t1*DD;
    const size_t R1OFF = (size_t)BB*HH*TT*DD;

    const float* Wp0 = W + (size_t)bkr * NTOT + bn + bn4 * 4;
    const float* Wp1 = W + (size_t)(8 + bkr) * NTOT + bn + bn4 * 4;

    const uint32_t bs_a0 = smem_u32(&Bs[0][bkr][bn4*4]);
    const uint32_t bs_a1 = smem_u32(&Bs[0][8+bkr][bn4*4]);
    const uint32_t bs_b0 = smem_u32(&Bs[1][bkr][bn4*4]);
    const uint32_t bs_b1 = smem_u32(&Bs[1][8+bkr][bn4*4]);

    cp_async16(bs_a0, Wp0);
    cp_async16(bs_a1, Wp1);
    CP_COMMIT();
    __syncthreads();   // wsm ready (needed for A compute below)

    float4 pa0, pa1;
    // compute A stage 0
    {
        const int k0 = 0;
        const int h = k0 >> 7;
        const size_t doff = (size_t)((k0 & 127) + akq*4);
        float2 w0v = wsm[arow][h], w1v = wsm[64+arow][h];
        float4 a0r0 = *(const float4*)(g_o + ob0 + (size_t)h*TT*DD + doff);
        float4 a0r1 = *(const float4*)(g_o + R1OFF + ob0 + (size_t)h*TT*DD + doff);
        float4 a1r0 = *(const float4*)(g_o + ob1 + (size_t)h*TT*DD + doff);
        float4 a1r1 = *(const float4*)(g_o + R1OFF + ob1 + (size_t)h*TT*DD + doff);
        pa0.x = w0v.x*a0r0.x + w0v.y*a0r1.x; pa0.y = w0v.x*a0r0.y + w0v.y*a0r1.y;
        pa0.z = w0v.x*a0r0.z + w0v.y*a0r1.z; pa0.w = w0v.x*a0r0.w + w0v.y*a0r1.w;
        pa1.x = w1v.x*a1r0.x + w1v.y*a1r1.x; pa1.y = w1v.x*a1r0.y + w1v.y*a1r1.y;
        pa1.z = w1v.x*a1r0.z + w1v.y*a1r1.z; pa1.w = w1v.x*a1r0.w + w1v.y*a1r1.w;
    }
    {
        const int kb = akq * 4;
        As[0][kb+0][arow]    = pa0.x; As[0][kb+1][arow]    = pa0.y;
        As[0][kb+2][arow]    = pa0.z; As[0][kb+3][arow]    = pa0.w;
        As[0][kb+0][64+arow] = pa1.x; As[0][kb+1][64+arow] = pa1.y;
        As[0][kb+2][64+arow] = pa1.z; As[0][kb+3][64+arow] = pa1.w;
    }
    CP_WAIT0();
    __syncthreads();

    u64 acc2[4][8];
    #pragma unroll
    for (int i = 0; i < 4; i++)
        #pragma unroll
        for (int j = 0; j < 8; j++) acc2[i][j] = 0ull;

    for (int s = 0; s < NST; s++) {
        const int buf = s & 1;
        if (s + 1 < NST) {
            const int k0 = (s + 1) * KS;
            const int h = k0 >> 7;
            const size_t doff = (size_t)((k0 & 127) + akq*4);
            float2 w0v = wsm[arow][h], w1v = wsm[64+arow][h];
            float4 a0r0 = *(const float4*)(g_o + ob0 + (size_t)h*TT*DD + doff);
            float4 a0r1 = *(const float4*)(g_o + R1OFF + ob0 + (size_t)h*TT*DD + doff);
            float4 a1r0 = *(const float4*)(g_o + ob1 + (size_t)h*TT*DD + doff);
            float4 a1r1 = *(const float4*)(g_o + R1OFF + ob1 + (size_t)h*TT*DD + doff);
            pa0.x = w0v.x*a0r0.x + w0v.y*a0r1.x; pa0.y = w0v.x*a0r0.y + w0v.y*a0r1.y;
            pa0.z = w0v.x*a0r0.z + w0v.y*a0r1.z; pa0.w = w0v.x*a0r0.w + w0v.y*a0r1.w;
            pa1.x = w1v.x*a1r0.x + w1v.y*a1r1.x; pa1.y = w1v.x*a1r0.y + w1v.y*a1r1.y;
            pa1.z = w1v.x*a1r0.z + w1v.y*a1r1.z; pa1.w = w1v.x*a1r0.w + w1v.y*a1r1.w;
            cp_async16(buf ? bs_a0 : bs_b0, Wp0 + (size_t)k0 * NTOT);
            cp_async16(buf ? bs_a1 : bs_b1, Wp1 + (size_t)k0 * NTOT);
            CP_COMMIT();
        }
        #pragma unroll
        for (int k = 0; k < KS; k++) {
            ulonglong2 a0 = *(const ulonglong2*)&As[buf][k][ty*4];
            ulonglong2 a1 = *(const ulonglong2*)&As[buf][k][64 + ty*4];
            float4 bv0 = *(const float4*)&Bs[buf][k][tx*4];
            float4 bv1 = *(const float4*)&Bs[buf][k][64 + tx*4];
            u64 ap[4] = {a0.x, a0.y, a1.x, a1.y};
            u64 bs2[8];
            SPLAT2(bs2[0], __float_as_uint(bv0.x));
            SPLAT2(bs2[1], __float_as_uint(bv0.y));
            SPLAT2(bs2[2], __float_as_uint(bv0.z));
            SPLAT2(bs2[3], __float_as_uint(bv0.w));
            SPLAT2(bs2[4], __float_as_uint(bv1.x));
            SPLAT2(bs2[5], __float_as_uint(bv1.y));
            SPLAT2(bs2[6], __float_as_uint(bv1.z));
            SPLAT2(bs2[7], __float_as_uint(bv1.w));
            #pragma unroll
            for (int i = 0; i < 4; i++)
                #pragma unroll
                for (int j = 0; j < 8; j++)
                    FMA2(acc2[i][j], ap[i], bs2[j]);
        }
        if (s + 1 < NST) {
            const int nb = buf ^ 1;
            __syncthreads();
            const int kb = akq * 4;
            As[nb][kb+0][arow]    = pa0.x; As[nb][kb+1][arow]    = pa0.y;
            As[nb][kb+2][arow]    = pa0.z; As[nb][kb+3][arow]    = pa0.w;
            As[nb][kb+0][64+arow] = pa1.x; As[nb][kb+1][64+arow] = pa1.y;
            As[nb][kb+2][64+arow] = pa1.z; As[nb][kb+3][64+arow] = pa1.w;
            CP_WAIT0();
            __syncthreads();
        }
    }

    #pragma unroll
    for (int i2 = 0; i2 < 4; i2++) {
        const int mrow = bm + ((i2 < 2) ? (ty*4 + i2*2) : (64 + ty*4 + (i2-2)*2));
        const int n0 = tx*4, n1 = 64 + tx*4;
        float* r0 = out + (size_t)mrow * NTOT + bn;
        float* r1 = out + (size_t)(mrow+1) * NTOT + bn;
        float4 lo0, lo1, hi0, hi1;
        lo0.x = lo_f(acc2[i2][0]) + bsm[n0+0]; hi0.x = hi_f(acc2[i2][0]) + bsm[n0+0];
        lo0.y = lo_f(acc2[i2][1]) + bsm[n0+1]; hi0.y = hi_f(acc2[i2][1]) + bsm[n0+1];
        lo0.z = lo_f(acc2[i2][2]) + bsm[n0+2]; hi0.z = hi_f(acc2[i2][2]) + bsm[n0+2];
        lo0.w = lo_f(acc2[i2][3]) + bsm[n0+3]; hi0.w = hi_f(acc2[i2][3]) + bsm[n0+3];
        lo1.x = lo_f(acc2[i2][4]) + bsm[n1+0]; hi1.x = hi_f(acc2[i2][4]) + bsm[n1+0];
        lo1.y = lo_f(acc2[i2][5]) + bsm[n1+1]; hi1.y = hi_f(acc2[i2][5]) + bsm[n1+1];
        lo1.z = lo_f(acc2[i2][6]) + bsm[n1+2]; hi1.z = hi_f(acc2[i2][6]) + bsm[n1+2];
        lo1.w = lo_f(acc2[i2][7]) + bsm[n1+3]; hi1.w = hi_f(acc2[i2][7]) + bsm[n1+3];
        *(float4*)(r0 + n0) = lo0;
        *(float4*)(r0 + n1) = lo1;
        *(float4*)(r1 + n0) = hi0;
        *(float4*)(r1 + n1) = hi1;
    }
}

// ==================== norm + hash (register-serial dots, no reductions) ====================
__global__ void __launch_bounds__(256) norm_hash_kernel(const float* __restrict__ hw)
{
    __shared__ float w_s[RR*HH*DD*4];   // 8192 floats = 32 KB
    int tid = threadIdx.x, lane = tid & 31, wp = tid >> 5;
    int tb0 = blockIdx.x * 16;

    #pragma unroll
    for (int i = 0; i < 8; i++)
        ((float4*)w_s)[tid + i*256] = ((const float4*)hw)[tid + i*256];

    #pragma unroll
    for (int rr = 0; rr < 2; rr++) {
        int tb = tb0 + wp*2 + rr;
        const float4* row = (const float4*)(g_qf + (size_t)tb*EE);
        float ss = 0.f;
        #pragma unroll
        for (int i = 0; i < 8; i++) {
            float4 v = row[lane + i*32];
            ss += v.x*v.x + v.y*v.y + v.z*v.z + v.w*v.w;
        }
        #pragma unroll
        for (int o = 16; o; o >>= 1) ss += __shfl_xor_sync(0xffffffffu, ss, o);
        if (lane == 0) g_invnorm[tb] = 1.0f / sqrtf(ss);
    }
    __syncthreads();

    int row = tid & 15, rh = tid >> 4;
    int r = rh >> 3, h = rh & 7;
    int tb = tb0 + row;
    int t = tb >> 1, b = tb & 1;
    const float4* x = (const float4*)(g_qf + (size_t)tb*EE + h*DD);
    const float4* wseg = (const float4*)(w_s + (r*HH + h)*DD*4);

    float l0 = 0.f, l1 = 0.f, l2 = 0.f, l3 = 0.f;
    #pragma unroll 8
    for (int d4 = 0; d4 < 32; d4++) {
        float4 xv = x[d4];
        float4 w0 = wseg[d4*4+0], w1 = wseg[d4*4+1];
        float4 w2 = wseg[d4*4+2], w3 = wseg[d4*4+3];
        l0 += xv.x*w0.x + xv.y*w1.x + xv.z*w2.x + xv.w*w3.x;
        l1 += xv.x*w0.y + xv.y*w1.y + xv.z*w2.y + xv.w*w3.y;
        l2 += xv.x*w0.z + xv.y*w1.z + xv.z*w2.z + xv.w*w3.z;
        l3 += xv.x*w0.w + xv.y*w1.w + xv.z*w2.w + xv.w*w3.w;
    }
    float best = l0; int bi = 0;
    if (l1 > best) { best = l1; bi = 1; }
    if (l2 > best) { best = l2; bi = 2; }
    if (l3 > best) { best = l3; bi = 3; }
    if (-l0 > best) { best = -l0; bi = 4; }
    if (-l1 > best) { best = -l1; bi = 5; }
    if (-l2 > best) { best = -l2; bi = 6; }
    if (-l3 > best) { best = -l3; bi = 7; }
    g_hash[((b*RR + r)*HH + h)*TT + t] = bi;
}

// ==================== stable counting sort (warp-parallel scan) ====================
__global__ void __launch_bounds__(256) sort_kernel()
{
    int brh = blockIdx.x;
    const int* hs = g_hash + brh*TT;
    int* pp = g_perm + brh*TT;
    int* iv = g_inv  + brh*TT;
    __shared__ int hist[256][9];
    __shared__ int btot[8], binbase[8];
    int tid = threadIdx.x, lane = tid & 31, wp = tid >> 5;
    int base = tid*8;
    int myh[8];
    int loc[8] = {0,0,0,0,0,0,0,0};
    #pragma unroll
    for (int i = 0; i < 8; i++) { int v = hs[base+i]; myh[i] = v; loc[v]++; }
    #pragma unroll
    for (int v = 0; v < 8; v++) hist[tid][v] = loc[v];
    __syncthreads();
    {
        int carry = 0;
        #pragma unroll
        for (int c = 0; c < 8; c++) {
            int v = hist[c*32 + lane][wp];
            int s = v;
            #pragma unroll
            for (int o = 1; o < 32; o <<= 1) {
                int n = __shfl_up_sync(0xffffffffu, s, o);
                if (lane >= o) s += n;
            }
            hist[c*32 + lane][wp] = carry + s - v;
            carry += __shfl_sync(0xffffffffu, s, 31);
        }
        if (lane == 0) btot[wp] = carry;
    }
    __syncthreads();
    if (tid == 0) {
        int s = 0;
        #pragma unroll
        for (int v = 0; v < 8; v++) { binbase[v] = s; s += btot[v]; }
    }
    __syncthreads();
    int off[8];
    #pragma unroll
    for (int v = 0; v < 8; v++) off[v] = binbase[v] + hist[tid][v];
    #pragma unroll
    for (int i = 0; i < 8; i++) {
        int v = myh[i];
        int pos = off[v]++;
        pp[pos] = base + i;
        iv[base + i] = pos;
    }
}

// ==================== chunked LSH attention (raw-k cp.async, k-side norm) ====================
#define QS 132
#define PS 100
#define ATTN_SMEM_BYTES (128*QS*4)   // 67584

__global__ void __launch_bounds__(256, 3) attn_kernel()
{
    extern __shared__ float sm[];
    float* k_s = sm;
    float* p_s = sm;
    __shared__ int s_kid[128], s_kh[128], s_ck[256];
    __shared__ float s_kinv[128];
    __shared__ u64 s_vp[128];
    __shared__ u64 s_qp[128];

    int bid = blockIdx.x;
    int cg = bid & 31;
    int h = (bid >> 5) & 7;
    int r = (bid >> 8) & 1;
    int b = bid >> 9;
    int brh = (b*RR + r)*HH + h;
    const int* pp = g_perm + brh*TT;
    int tid = threadIdx.x, lane = tid & 31, wp = tid >> 5;

    if (tid < 128) {
        int wc = (cg*2 + (tid >> 5) + CC - 1) & (CC - 1);
        int kid = pp[wc*32 + (tid & 31)];
        s_kid[tid] = kid;
        s_kh[tid] = g_hash[brh*TT + kid];
        s_kinv[tid] = g_invnorm[kid*BB + b];
        s_ck[tid*2+0] = g_inv[((b*RR+0)*HH+h)*TT + kid] >> 5;
        s_ck[tid*2+1] = g_inv[((b*RR+1)*HH+h)*TT + kid] >> 5;
        size_t rowoff = (size_t)kid*(BB*EE) + (size_t)b*EE + h*DD;
        s_vp[tid] = (u64)(g_vf + rowoff);
        s_qp[tid] = (u64)(g_qf + rowoff);
    }
    __syncthreads();

    {
        uint32_t ksb = smem_u32(k_s);
        for (int idx = tid; idx < 128*32; idx += 256) {
            int j = idx >> 5, d4 = idx & 31;
            cp_async16(ksb + (uint32_t)(j*QS + d4*4)*4u, (const float*)s_qp[j] + d4*4);
        }
        CP_COMMIT();
        CP_WAIT0();
    }
    __syncthreads();

    const int kb = (wp >> 2) * 32;
    const int l0 = wp * 8;

    u64 acc2[8][3];
    #pragma unroll
    for (int i = 0; i < 8; i++) { acc2[i][0]=0ull; acc2[i][1]=0ull; acc2[i][2]=0ull; }
    {
        const float* kp0 = k_s + (kb + lane)*QS;
        const float* kp1 = kp0 + 32*QS;
        const float* kp2 = kp0 + 64*QS;
        const float* qp  = k_s + (32 + l0)*QS;
        #pragma unroll 2
        for (int d4 = 0; d4 < 32; d4++) {
            ulonglong2 k0 = *(const ulonglong2*)(kp0 + d4*4);
            ulonglong2 k1 = *(const ulonglong2*)(kp1 + d4*4);
            ulonglong2 k2 = *(const ulonglong2*)(kp2 + d4*4);
            #pragma unroll
            for (int i = 0; i < 8; i++) {
                ulonglong2 qv = *(const ulonglong2*)(qp + i*QS + d4*4);
                FMA2(acc2[i][0], qv.x, k0.x); FMA2(acc2[i][0], qv.y, k0.y);
                FMA2(acc2[i][1], qv.x, k1.x); FMA2(acc2[i][1], qv.y, k1.y);
                FMA2(acc2[i][2], qv.x, k2.x); FMA2(acc2[i][2], qv.y, k2.y);
            }
        }
    }
    float acc[8][3];
    #pragma unroll
    for (int i = 0; i < 8; i++)
        #pragma unroll
        for (int mi = 0; mi < 3; mi++)
            acc[i][mi] = lo_f(acc2[i][mi]) + hi_f(acc2[i][mi]);

    const float scale = 0.08838834764831845f;  // 128^-0.5
    {
        int khv[3], kidv[3], ck0[3], ck1[3];
        float kf[3];
        #pragma unroll
        for (int mi = 0; mi < 3; mi++) {
            int m = kb + mi*32 + lane;
            khv[mi] = s_kh[m]; kidv[mi] = s_kid[m];
            ck0[mi] = s_ck[m*2+0]; ck1[mi] = s_ck[m*2+1];
            kf[mi] = scale * s_kinv[m];
        }
        #pragma unroll
        for (int i = 0; i < 8; i++) {
            int row = 32 + l0 + i;
            int qh = s_kh[row], qid = s_kid[row];
            int cq0 = s_ck[row*2], cq1 = s_ck[row*2+1];
            #pragma unroll
            for (int mi = 0; mi < 3; mi++) {
                float s = acc[i][mi] * kf[mi];
                if (qh != khv[mi])   s -= 1.0e16f;
                if (qid == kidv[mi]) s -= 1.0e8f;
                int d0 = (ck0[mi] - cq0) & (CC-1);
                int d1 = (ck1[mi] - cq1) & (CC-1);
                int dup = ((d0 <= 1) | (d0 == CC-1)) + ((d1 <= 1) | (d1 == CC-1));
                if (dup == 2) s -= 0.6931471805599453f;
                acc[i][mi] = s;
            }
            float mx = fmaxf(acc[i][0], fmaxf(acc[i][1], acc[i][2]));
            #pragma unroll
            for (int o = 16; o; o >>= 1) mx = fmaxf(mx, __shfl_xor_sync(0xffffffffu, mx, o));
            float p0 = __expf(acc[i][0]-mx), p1 = __expf(acc[i][1]-mx), p2 = __expf(acc[i][2]-mx);
            float sum = p0 + p1 + p2;
            #pragma unroll
            for (int o = 16; o; o >>= 1) sum += __shfl_xor_sync(0xffffffffu, sum, o);
            float rinv = 1.0f / sum;
            acc[i][0] = p0*rinv; acc[i][1] = p1*rinv; acc[i][2] = p2*rinv;
            if (lane == 0) g_z[((r*BB + b)*HH + h)*TT + qid] = __logf(sum) + mx;
        }
    }
    __syncthreads();

    #pragma unroll
    for (int i = 0; i < 8; i++) {
        float* pr = p_s + (l0 + i)*PS;
        pr[lane]      = acc[i][0];
        pr[32 + lane] = acc[i][1];
        pr[64 + lane] = acc[i][2];
    }
    __syncthreads();

    {
        const int dbase = lane*4;
        u64 o01[8], o23[8];
        #pragma unroll
        for (int i = 0; i < 8; i++) { o01[i]=0ull; o23[i]=0ull; }
        #pragma unroll 2
        for (int m4 = 0; m4 < 24; m4++) {
            int m0 = kb + m4*4;
            ulonglong2 v0 = *(const ulonglong2*)((const float*)s_vp[m0+0] + dbase);
            ulonglong2 v1 = *(const ulonglong2*)((const float*)s_vp[m0+1] + dbase);
            ulonglong2 v2 = *(const ulonglong2*)((const float*)s_vp[m0+2] + dbase);
            ulonglong2 v3 = *(const ulonglong2*)((const float*)s_vp[m0+3] + dbase);
            #pragma unroll
            for (int i = 0; i < 8; i++) {
                float4 pv = *(const float4*)&p_s[(l0+i)*PS + m4*4];
                u64 s0, s1, s2, s3;
                SPLAT2(s0, __float_as_uint(pv.x));
                SPLAT2(s1, __float_as_uint(pv.y));
                SPLAT2(s2, __float_as_uint(pv.z));
                SPLAT2(s3, __float_as_uint(pv.w));
                FMA2(o01[i], s0, v0.x); FMA2(o23[i], s0, v0.y);
                FMA2(o01[i], s1, v1.x); FMA2(o23[i], s1, v1.y);
                FMA2(o01[i], s2, v2.x); FMA2(o23[i], s2, v2.y);
                FMA2(o01[i], s3, v3.x); FMA2(o23[i], s3, v3.y);
            }
        }
        #pragma unroll
        for (int i = 0; i < 8; i++) {
            int qid = s_kid[32 + l0 + i];
            float* op = g_o + ((size_t)((r*BB + b)*HH + h)*TT + qid)*DD + dbase;
            *(float4*)op = make_float4(lo_f(o01[i]), hi_f(o01[i]), lo_f(o23[i]), hi_f(o23[i]));
        }
    }
}

// ==================== launch ====================
extern "C" void kernel_launch(void* const* d_in, const int* in_sizes, int n_in,
                              void* d_out, int out_size)
{
    const float* query = (const float*)d_in[0];
    const float* value = (const float*)d_in[2];
    const float* Wq = (const float*)d_in[3];
    const float* bq = (const float*)d_in[4];
    const float* Wv = (const float*)d_in[5];
    const float* bv = (const float*)d_in[6];
    const float* Wo = (const float*)d_in[7];
    const float* bo = (const float*)d_in[8];
    const float* hw = (const float*)d_in[9];

    float* qf;  cudaGetSymbolAddress((void**)&qf,  g_qf);
    float* vf;  cudaGetSymbolAddress((void**)&vf,  g_vf);

    cudaFuncSetAttribute(attn_kernel, cudaFuncAttributeMaxDynamicSharedMemorySize, ATTN_SMEM_BYTES);

    dim3 gqv(NTOT/128, (TT*BB)/128, 2);   // fused Wq + Wv projections
    dim3 go (NTOT/128, (TT*BB)/128);      // Wo projection (combine fused)

    sgemm_kernel<<<gqv, 256>>>(query, Wq, bq, qf, value, Wv, bv, vf);
    norm_hash_kernel<<<(TT*BB)/16, 256>>>(hw);
    sort_kernel<<<BB*RR*HH, 256>>>();
    attn_kernel<<<BB*RR*HH*32, 256, ATTN_SMEM_BYTES>>>();
    sgemm_wo_kernel<<<go, 256>>>(Wo, bo, (float*)d_out);
}

// round 14
// speedup vs baseline: 1.0319x; 1.0319x over previous
#include <cuda_runtime.h>
#include <math.h>
#include <stdint.h>

// Problem constants
#define TT 2048
#define BB 2
#define EE 1024
#define HH 8
#define DD 128
#define RR 2
#define CHUNKC 32
#define CC (TT/CHUNKC)   // 64
#define KTOT 1024
#define NTOT 1024

typedef unsigned long long u64;

// packed f32x2 helpers (sm_100+ PTX; ptxas never auto-fuses these)
#define FMA2(acc, x, y) \
    asm("fma.rn.f32x2 %0, %1, %2, %0;" : "+l"(acc) : "l"(x), "l"(y))
#define SPLAT2(d, s) \
    asm("mov.b64 %0, {%1, %1};" : "=l"(d) : "r"(s))

__device__ __forceinline__ float lo_f(u64 v) { return __uint_as_float((uint32_t)v); }
__device__ __forceinline__ float hi_f(u64 v) { return __uint_as_float((uint32_t)(v >> 32)); }

__device__ __forceinline__ uint32_t smem_u32(const void* p) {
    uint32_t a;
    asm("{ .reg .u64 t; cvta.to.shared.u64 t, %1; cvt.u32.u64 %0, t; }" : "=r"(a) : "l"(p));
    return a;
}
__device__ __forceinline__ void cp_async16(uint32_t smem_addr, const void* gptr) {
    asm volatile("cp.async.ca.shared.global [%0], [%1], 16;" :: "r"(smem_addr), "l"(gptr));
}
#define CP_COMMIT() asm volatile("cp.async.commit_group;" ::: "memory")
#define CP_WAIT0()  asm volatile("cp.async.wait_group 0;" ::: "memory")

// -------------------- device scratch --------------------
__device__ float g_qf[TT*BB*EE];
__device__ float g_vf[TT*BB*EE];
__device__ float g_ctx[TT*BB*EE];
__device__ float g_invnorm[TT*BB];
__device__ int   g_hash[BB*RR*HH*TT];
__device__ int   g_perm[BB*RR*HH*TT];
__device__ int   g_inv [BB*RR*HH*TT];
__device__ float g_o[RR*BB*HH*TT*DD];
__device__ float g_z[RR*BB*HH*TT];

// ==================== exact-fp32 SGEMM (f32x2 + cp.async B): out = A @ W + bias ====================
#define KS 16
#define NST (KTOT/KS)   // 64

__global__ void __launch_bounds__(256, 2) sgemm_kernel(
    const float* __restrict__ A0, const float* __restrict__ W0,
    const float* __restrict__ b0, float* __restrict__ o0,
    const float* __restrict__ A1, const float* __restrict__ W1,
    const float* __restrict__ b1, float* __restrict__ o1)
{
    const float* A    = blockIdx.z ? A1 : A0;
    const float* W    = blockIdx.z ? W1 : W0;
    const float* bias = blockIdx.z ? b1 : b0;
    float*       out  = blockIdx.z ? o1 : o0;

    __shared__ __align__(16) float As[2][KS][132];
    __shared__ __align__(16) float Bs[2][KS][128];
    __shared__ float bsm[128];

    const int tid = threadIdx.x;
    const int bm = blockIdx.y * 128;
    const int bn = blockIdx.x * 128;
    const int tx = tid & 15;
    const int ty = tid >> 4;

    if (tid < 128) bsm[tid] = bias[bn + tid];

    const int arow = tid >> 2;
    const int akq  = tid & 3;
    const int bkr = tid >> 5;
    const int bn4 = tid & 31;

    const float* Ap0 = A + (size_t)(bm + arow) * KTOT + akq * 4;
    const float* Ap1 = A + (size_t)(bm + 64 + arow) * KTOT + akq * 4;
    const float* Wp0 = W + (size_t)bkr * NTOT + bn + bn4 * 4;
    const float* Wp1 = W + (size_t)(8 + bkr) * NTOT + bn + bn4 * 4;

    const uint32_t bs_a0 = smem_u32(&Bs[0][bkr][bn4*4]);
    const uint32_t bs_a1 = smem_u32(&Bs[0][8+bkr][bn4*4]);
    const uint32_t bs_b0 = smem_u32(&Bs[1][bkr][bn4*4]);
    const uint32_t bs_b1 = smem_u32(&Bs[1][8+bkr][bn4*4]);

    float4 pa0, pa1;
    u64 acc2[4][8];
    #pragma unroll
    for (int i = 0; i < 4; i++)
        #pragma unroll
        for (int j = 0; j < 8; j++) acc2[i][j] = 0ull;

    pa0 = *(const float4*)(Ap0);
    pa1 = *(const float4*)(Ap1);
    cp_async16(bs_a0, Wp0);
    cp_async16(bs_a1, Wp1);
    CP_COMMIT();
    {
        const int kb = akq * 4;
        As[0][kb+0][arow]    = pa0.x; As[0][kb+1][arow]    = pa0.y;
        As[0][kb+2][arow]    = pa0.z; As[0][kb+3][arow]    = pa0.w;
        As[0][kb+0][64+arow] = pa1.x; As[0][kb+1][64+arow] = pa1.y;
        As[0][kb+2][64+arow] = pa1.z; As[0][kb+3][64+arow] = pa1.w;
    }
    CP_WAIT0();
    __syncthreads();

    for (int s = 0; s < NST; s++) {
        const int buf = s & 1;
        if (s + 1 < NST) {
            const size_t ko = (size_t)(s + 1) * KS;
            pa0 = *(const float4*)(Ap0 + ko);
            pa1 = *(const float4*)(Ap1 + ko);
            cp_async16(buf ? bs_a0 : bs_b0, Wp0 + ko * NTOT);
            cp_async16(buf ? bs_a1 : bs_b1, Wp1 + ko * NTOT);
            CP_COMMIT();
        }
        #pragma unroll
        for (int k = 0; k < KS; k++) {
            ulonglong2 a0 = *(const ulonglong2*)&As[buf][k][ty*4];
            ulonglong2 a1 = *(const ulonglong2*)&As[buf][k][64 + ty*4];
            float4 bv0 = *(const float4*)&Bs[buf][k][tx*4];
            float4 bv1 = *(const float4*)&Bs[buf][k][64 + tx*4];
            u64 ap[4] = {a0.x, a0.y, a1.x, a1.y};
            u64 bs2[8];
            SPLAT2(bs2[0], __float_as_uint(bv0.x));
            SPLAT2(bs2[1], __float_as_uint(bv0.y));
            SPLAT2(bs2[2], __float_as_uint(bv0.z));
            SPLAT2(bs2[3], __float_as_uint(bv0.w));
            SPLAT2(bs2[4], __float_as_uint(bv1.x));
            SPLAT2(bs2[5], __float_as_uint(bv1.y));
            SPLAT2(bs2[6], __float_as_uint(bv1.z));
            SPLAT2(bs2[7], __float_as_uint(bv1.w));
            #pragma unroll
            for (int i = 0; i < 4; i++)
                #pragma unroll
                for (int j = 0; j < 8; j++)
                    FMA2(acc2[i][j], ap[i], bs2[j]);
        }
        if (s + 1 < NST) {
            const int nb = buf ^ 1;
            __syncthreads();
            const int kb = akq * 4;
            As[nb][kb+0][arow]    = pa0.x; As[nb][kb+1][arow]    = pa0.y;
            As[nb][kb+2][arow]    = pa0.z; As[nb][kb+3][arow]    = pa0.w;
            As[nb][kb+0][64+arow] = pa1.x; As[nb][kb+1][64+arow] = pa1.y;
            As[nb][kb+2][64+arow] = pa1.z; As[nb][kb+3][64+arow] = pa1.w;
            CP_WAIT0();
            __syncthreads();
        }
    }

    #pragma unroll
    for (int i2 = 0; i2 < 4; i2++) {
        const int mrow = bm + ((i2 < 2) ? (ty*4 + i2*2) : (64 + ty*4 + (i2-2)*2));
        const int n0 = tx*4, n1 = 64 + tx*4;
        float* r0 = out + (size_t)mrow * NTOT + bn;
        float* r1 = out + (size_t)(mrow+1) * NTOT + bn;
        float4 lo0, lo1, hi0, hi1;
        lo0.x = lo_f(acc2[i2][0]) + bsm[n0+0]; hi0.x = hi_f(acc2[i2][0]) + bsm[n0+0];
        lo0.y = lo_f(acc2[i2][1]) + bsm[n0+1]; hi0.y = hi_f(acc2[i2][1]) + bsm[n0+1];
        lo0.z = lo_f(acc2[i2][2]) + bsm[n0+2]; hi0.z = hi_f(acc2[i2][2]) + bsm[n0+2];
        lo0.w = lo_f(acc2[i2][3]) + bsm[n0+3]; hi0.w = hi_f(acc2[i2][3]) + bsm[n0+3];
        lo1.x = lo_f(acc2[i2][4]) + bsm[n1+0]; hi1.x = hi_f(acc2[i2][4]) + bsm[n1+0];
        lo1.y = lo_f(acc2[i2][5]) + bsm[n1+1]; hi1.y = hi_f(acc2[i2][5]) + bsm[n1+1];
        lo1.z = lo_f(acc2[i2][6]) + bsm[n1+2]; hi1.z = hi_f(acc2[i2][6]) + bsm[n1+2];
        lo1.w = lo_f(acc2[i2][7]) + bsm[n1+3]; hi1.w = hi_f(acc2[i2][7]) + bsm[n1+3];
        *(float4*)(r0 + n0) = lo0;
        *(float4*)(r0 + n1) = lo1;
        *(float4*)(r1 + n0) = hi0;
        *(float4*)(r1 + n1) = hi1;
    }
}

// ==================== norm + hash (register-serial dots, no reductions) ====================
__global__ void __launch_bounds__(256) norm_hash_kernel(const float* __restrict__ hw)
{
    __shared__ float w_s[RR*HH*DD*4];   // 8192 floats = 32 KB
    int tid = threadIdx.x, lane = tid & 31, wp = tid >> 5;
    int tb0 = blockIdx.x * 16;

    #pragma unroll
    for (int i = 0; i < 8; i++)
        ((float4*)w_s)[tid + i*256] = ((const float4*)hw)[tid + i*256];

    #pragma unroll
    for (int rr = 0; rr < 2; rr++) {
        int tb = tb0 + wp*2 + rr;
        const float4* row = (const float4*)(g_qf + (size_t)tb*EE);
        float ss = 0.f;
        #pragma unroll
        for (int i = 0; i < 8; i++) {
            float4 v = row[lane + i*32];
            ss += v.x*v.x + v.y*v.y + v.z*v.z + v.w*v.w;
        }
        #pragma unroll
        for (int o = 16; o; o >>= 1) ss += __shfl_xor_sync(0xffffffffu, ss, o);
        if (lane == 0) g_invnorm[tb] = 1.0f / sqrtf(ss);
    }
    __syncthreads();

    int row = tid & 15, rh = tid >> 4;
    int r = rh >> 3, h = rh & 7;
    int tb = tb0 + row;
    int t = tb >> 1, b = tb & 1;
    const float4* x = (const float4*)(g_qf + (size_t)tb*EE + h*DD);
    const float4* wseg = (const float4*)(w_s + (r*HH + h)*DD*4);

    float l0 = 0.f, l1 = 0.f, l2 = 0.f, l3 = 0.f;
    #pragma unroll 8
    for (int d4 = 0; d4 < 32; d4++) {
        float4 xv = x[d4];
        float4 w0 = wseg[d4*4+0], w1 = wseg[d4*4+1];
        float4 w2 = wseg[d4*4+2], w3 = wseg[d4*4+3];
        l0 += xv.x*w0.x + xv.y*w1.x + xv.z*w2.x + xv.w*w3.x;
        l1 += xv.x*w0.y + xv.y*w1.y + xv.z*w2.y + xv.w*w3.y;
        l2 += xv.x*w0.z + xv.y*w1.z + xv.z*w2.z + xv.w*w3.z;
        l3 += xv.x*w0.w + xv.y*w1.w + xv.z*w2.w + xv.w*w3.w;
    }
    float best = l0; int bi = 0;
    if (l1 > best) { best = l1; bi = 1; }
    if (l2 > best) { best = l2; bi = 2; }
    if (l3 > best) { best = l3; bi = 3; }
    if (-l0 > best) { best = -l0; bi = 4; }
    if (-l1 > best) { best = -l1; bi = 5; }
    if (-l2 > best) { best = -l2; bi = 6; }
    if (-l3 > best) { best = -l3; bi = 7; }
    g_hash[((b*RR + r)*HH + h)*TT + t] = bi;
}

// ==================== stable counting sort (warp-parallel scan) ====================
__global__ void __launch_bounds__(256) sort_kernel()
{
    int brh = blockIdx.x;
    const int* hs = g_hash + brh*TT;
    int* pp = g_perm + brh*TT;
    int* iv = g_inv  + brh*TT;
    __shared__ int hist[256][9];     // padded: conflict-free column scans
    __shared__ int btot[8], binbase[8];
    int tid = threadIdx.x, lane = tid & 31, wp = tid >> 5;
    int base = tid*8;
    int myh[8];
    int loc[8] = {0,0,0,0,0,0,0,0};
    #pragma unroll
    for (int i = 0; i < 8; i++) { int v = hs[base+i]; myh[i] = v; loc[v]++; }
    #pragma unroll
    for (int v = 0; v < 8; v++) hist[tid][v] = loc[v];
    __syncthreads();
    {
        int carry = 0;
        #pragma unroll
        for (int c = 0; c < 8; c++) {
            int v = hist[c*32 + lane][wp];
            int s = v;
            #pragma unroll
            for (int o = 1; o < 32; o <<= 1) {
                int n = __shfl_up_sync(0xffffffffu, s, o);
                if (lane >= o) s += n;
            }
            hist[c*32 + lane][wp] = carry + s - v;   // exclusive
            carry += __shfl_sync(0xffffffffu, s, 31);
        }
        if (lane == 0) btot[wp] = carry;
    }
    __syncthreads();
    if (tid == 0) {
        int s = 0;
        #pragma unroll
        for (int v = 0; v < 8; v++) { binbase[v] = s; s += btot[v]; }
    }
    __syncthreads();
    int off[8];
    #pragma unroll
    for (int v = 0; v < 8; v++) off[v] = binbase[v] + hist[tid][v];
    #pragma unroll
    for (int i = 0; i < 8; i++) {
        int v = myh[i];
        int pos = off[v]++;
        pp[pos] = base + i;
        iv[base + i] = pos;
    }
}

// ==================== chunked LSH attention (raw-k cp.async, k-side norm) ====================
#define QS 132
#define PS 100
#define ATTN_SMEM_BYTES (128*QS*4)   // 67584

__global__ void __launch_bounds__(256, 3) attn_kernel()
{
    extern __shared__ float sm[];
    float* k_s = sm;                 // 128 x 132 (raw qf rows)
    float* p_s = sm;                 // aliases k_s after QK: 64 x 100
    __shared__ int s_kid[128], s_kh[128], s_ck[256];
    __shared__ float s_kinv[128];
    __shared__ u64 s_vp[128];
    __shared__ u64 s_qp[128];

    int bid = blockIdx.x;
    int cg = bid & 31;
    int h = (bid >> 5) & 7;
    int r = (bid >> 8) & 1;
    int b = bid >> 9;
    int brh = (b*RR + r)*HH + h;
    const int* pp = g_perm + brh*TT;
    int tid = threadIdx.x, lane = tid & 31, wp = tid >> 5;

    if (tid < 128) {
        int wc = (cg*2 + (tid >> 5) + CC - 1) & (CC - 1);
        int kid = pp[wc*32 + (tid & 31)];
        s_kid[tid] = kid;
        s_kh[tid] = g_hash[brh*TT + kid];
        s_kinv[tid] = g_invnorm[kid*BB + b];
        s_ck[tid*2+0] = g_inv[((b*RR+0)*HH+h)*TT + kid] >> 5;
        s_ck[tid*2+1] = g_inv[((b*RR+1)*HH+h)*TT + kid] >> 5;
        size_t rowoff = (size_t)kid*(BB*EE) + (size_t)b*EE + h*DD;
        s_vp[tid] = (u64)(g_vf + rowoff);
        s_qp[tid] = (u64)(g_qf + rowoff);
    }
    __syncthreads();

    {
        uint32_t ksb = smem_u32(k_s);
        for (int idx = tid; idx < 128*32; idx += 256) {
            int j = idx >> 5, d4 = idx & 31;
            cp_async16(ksb + (uint32_t)(j*QS + d4*4)*4u, (const float*)s_qp[j] + d4*4);
        }
        CP_COMMIT();
        CP_WAIT0();
    }
    __syncthreads();

    const int kb = (wp >> 2) * 32;
    const int l0 = wp * 8;

    u64 acc2[8][3];
    #pragma unroll
    for (int i = 0; i < 8; i++) { acc2[i][0]=0ull; acc2[i][1]=0ull; acc2[i][2]=0ull; }
    {
        const float* kp0 = k_s + (kb + lane)*QS;
        const float* kp1 = kp0 + 32*QS;
        const float* kp2 = kp0 + 64*QS;
        const float* qp  = k_s + (32 + l0)*QS;
        #pragma unroll 2
        for (int d4 = 0; d4 < 32; d4++) {
            ulonglong2 k0 = *(const ulonglong2*)(kp0 + d4*4);
            ulonglong2 k1 = *(const ulonglong2*)(kp1 + d4*4);
            ulonglong2 k2 = *(const ulonglong2*)(kp2 + d4*4);
            #pragma unroll
            for (int i = 0; i < 8; i++) {
                ulonglong2 qv = *(const ulonglong2*)(qp + i*QS + d4*4);
                FMA2(acc2[i][0], qv.x, k0.x); FMA2(acc2[i][0], qv.y, k0.y);
                FMA2(acc2[i][1], qv.x, k1.x); FMA2(acc2[i][1], qv.y, k1.y);
                FMA2(acc2[i][2], qv.x, k2.x); FMA2(acc2[i][2], qv.y, k2.y);
            }
        }
    }
    float acc[8][3];
    #pragma unroll
    for (int i = 0; i < 8; i++)
        #pragma unroll
        for (int mi = 0; mi < 3; mi++)
            acc[i][mi] = lo_f(acc2[i][mi]) + hi_f(acc2[i][mi]);

    const float scale = 0.08838834764831845f;  // 128^-0.5
    {
        int khv[3], kidv[3], ck0[3], ck1[3];
        float kf[3];
        #pragma unroll
        for (int mi = 0; mi < 3; mi++) {
            int m = kb + mi*32 + lane;
            khv[mi] = s_kh[m]; kidv[mi] = s_kid[m];
            ck0[mi] = s_ck[m*2+0]; ck1[mi] = s_ck[m*2+1];
            kf[mi] = scale * s_kinv[m];
        }
        #pragma unroll
        for (int i = 0; i < 8; i++) {
            int row = 32 + l0 + i;
            int qh = s_kh[row], qid = s_kid[row];
            int cq0 = s_ck[row*2], cq1 = s_ck[row*2+1];
            #pragma unroll
            for (int mi = 0; mi < 3; mi++) {
                float s = acc[i][mi] * kf[mi];
                if (qh != khv[mi])   s -= 1.0e16f;
                if (qid == kidv[mi]) s -= 1.0e8f;
                int d0 = (ck0[mi] - cq0) & (CC-1);
                int d1 = (ck1[mi] - cq1) & (CC-1);
                int dup = ((d0 <= 1) | (d0 == CC-1)) + ((d1 <= 1) | (d1 == CC-1));
                if (dup == 2) s -= 0.6931471805599453f;
                acc[i][mi] = s;
            }
            float mx = fmaxf(acc[i][0], fmaxf(acc[i][1], acc[i][2]));
            #pragma unroll
            for (int o = 16; o; o >>= 1) mx = fmaxf(mx, __shfl_xor_sync(0xffffffffu, mx, o));
            float p0 = __expf(acc[i][0]-mx), p1 = __expf(acc[i][1]-mx), p2 = __expf(acc[i][2]-mx);
            float sum = p0 + p1 + p2;
            #pragma unroll
            for (int o = 16; o; o >>= 1) sum += __shfl_xor_sync(0xffffffffu, sum, o);
            float rinv = 1.0f / sum;
            acc[i][0] = p0*rinv; acc[i][1] = p1*rinv; acc[i][2] = p2*rinv;
            if (lane == 0) g_z[((r*BB + b)*HH + h)*TT + qid] = __logf(sum) + mx;
        }
    }
    __syncthreads();

    #pragma unroll
    for (int i = 0; i < 8; i++) {
        float* pr = p_s + (l0 + i)*PS;
        pr[lane]      = acc[i][0];
        pr[32 + lane] = acc[i][1];
        pr[64 + lane] = acc[i][2];
    }
    __syncthreads();

    {
        const int dbase = lane*4;
        u64 o01[8], o23[8];
        #pragma unroll
        for (int i = 0; i < 8; i++) { o01[i]=0ull; o23[i]=0ull; }
        #pragma unroll 2
        for (int m4 = 0; m4 < 24; m4++) {
            int m0 = kb + m4*4;
            ulonglong2 v0 = *(const ulonglong2*)((const float*)s_vp[m0+0] + dbase);
            ulonglong2 v1 = *(const ulonglong2*)((const float*)s_vp[m0+1] + dbase);
            ulonglong2 v2 = *(const ulonglong2*)((const float*)s_vp[m0+2] + dbase);
            ulonglong2 v3 = *(const ulonglong2*)((const float*)s_vp[m0+3] + dbase);
            #pragma unroll
            for (int i = 0; i < 8; i++) {
                float4 pv = *(const float4*)&p_s[(l0+i)*PS + m4*4];
                u64 s0, s1, s2, s3;
                SPLAT2(s0, __float_as_uint(pv.x));
                SPLAT2(s1, __float_as_uint(pv.y));
                SPLAT2(s2, __float_as_uint(pv.z));
                SPLAT2(s3, __float_as_uint(pv.w));
                FMA2(o01[i], s0, v0.x); FMA2(o23[i], s0, v0.y);
                FMA2(o01[i], s1, v1.x); FMA2(o23[i], s1, v1.y);
                FMA2(o01[i], s2, v2.x); FMA2(o23[i], s2, v2.y);
                FMA2(o01[i], s3, v3.x); FMA2(o23[i], s3, v3.y);
            }
        }
        #pragma unroll
        for (int i = 0; i < 8; i++) {
            int qid = s_kid[32 + l0 + i];
            float* op = g_o + ((size_t)((r*BB + b)*HH + h)*TT + qid)*DD + dbase;
            *(float4*)op = make_float4(lo_f(o01[i]), hi_f(o01[i]), lo_f(o23[i]), hi_f(o23[i]));
        }
    }
}

// ==================== round combination (float4) ====================
__global__ void __launch_bounds__(256) combine_kernel()
{
    int idx = blockIdx.x*256 + threadIdx.x;   // over B*H*T*D/4 = 2^20
    int d4 = idx & 31;
    int t = (idx >> 5) & 2047;
    int h = (idx >> 16) & 7;
    int b = idx >> 19;
    int zi = (b*HH + h)*TT + t;
    float z0 = g_z[zi];
    float z1 = g_z[BB*HH*TT + zi];
    float mz = fmaxf(z0, z1);
    float e0 = __expf(z0 - mz), e1 = __expf(z1 - mz);
    float winv = 1.0f / (e0 + e1);
    float w0 = e0 * winv, w1 = e1 * winv;
    const float4* o4 = (const float4*)g_o;
    int oi = ((b*HH + h)*TT + t)*32 + d4;
    float4 v0 = o4[oi];
    float4 v1 = o4[BB*HH*TT*32 + oi];
    float4 out;
    out.x = w0*v0.x + w1*v1.x;
    out.y = w0*v0.y + w1*v1.y;
    out.z = w0*v0.z + w1*v1.z;
    out.w = w0*v0.w + w1*v1.w;
    ((float4*)g_ctx)[(t*BB + b)*256 + h*32 + d4] = out;
}

// ==================== launch ====================
extern "C" void kernel_launch(void* const* d_in, const int* in_sizes, int n_in,
                              void* d_out, int out_size)
{
    const float* query = (const float*)d_in[0];
    const float* value = (const float*)d_in[2];
    const float* Wq = (const float*)d_in[3];
    const float* bq = (const float*)d_in[4];
    const float* Wv = (const float*)d_in[5];
    const float* bv = (const float*)d_in[6];
    const float* Wo = (const float*)d_in[7];
    const float* bo = (const float*)d_in[8];
    const float* hw = (const float*)d_in[9];

    float* qf;  cudaGetSymbolAddress((void**)&qf,  g_qf);
    float* vf;  cudaGetSymbolAddress((void**)&vf,  g_vf);
    float* ctx; cudaGetSymbolAddress((void**)&ctx, g_ctx);

    cudaFuncSetAttribute(attn_kernel, cudaFuncAttributeMaxDynamicSharedMemorySize, ATTN_SMEM_BYTES);

    dim3 gqv(NTOT/128, (TT*BB)/128, 2);   // fused Wq + Wv projections
    dim3 go (NTOT/128, (TT*BB)/128, 1);   // Wo projection

    sgemm_kernel<<<gqv, 256>>>(query, Wq, bq, qf, value, Wv, bv, vf);
    norm_hash_kernel<<<(TT*BB)/16, 256>>>(hw);
    sort_kernel<<<BB*RR*HH, 256>>>();
    attn_kernel<<<BB*RR*HH*32, 256, ATTN_SMEM_BYTES>>>();
    combine_kernel<<<(BB*HH*TT*DD/4)/256, 256>>>();
    sgemm_kernel<<<go, 256>>>(ctx, Wo, bo, (float*)d_out,
                              ctx, Wo, bo, (float*)d_out);
}

// round 15
// speedup vs baseline: 1.0342x; 1.0022x over previous
#include <cuda_runtime.h>
#include <math.h>
#include <stdint.h>

// Problem constants
#define TT 2048
#define BB 2
#define EE 1024
#define HH 8
#define DD 128
#define RR 2
#define CHUNKC 32
#define CC (TT/CHUNKC)   // 64
#define KTOT 1024
#define NTOT 1024

typedef unsigned long long u64;

// packed f32x2 helpers (sm_100+ PTX; ptxas never auto-fuses these)
#define FMA2(acc, x, y) \
    asm("fma.rn.f32x2 %0, %1, %2, %0;" : "+l"(acc) : "l"(x), "l"(y))
#define SPLAT2(d, s) \
    asm("mov.b64 %0, {%1, %1};" : "=l"(d) : "r"(s))

__device__ __forceinline__ float lo_f(u64 v) { return __uint_as_float((uint32_t)v); }
__device__ __forceinline__ float hi_f(u64 v) { return __uint_as_float((uint32_t)(v >> 32)); }

__device__ __forceinline__ uint32_t smem_u32(const void* p) {
    uint32_t a;
    asm("{ .reg .u64 t; cvta.to.shared.u64 t, %1; cvt.u32.u64 %0, t; }" : "=r"(a) : "l"(p));
    return a;
}
__device__ __forceinline__ void cp_async16(uint32_t smem_addr, const void* gptr) {
    asm volatile("cp.async.ca.shared.global [%0], [%1], 16;" :: "r"(smem_addr), "l"(gptr));
}
#define CP_COMMIT() asm volatile("cp.async.commit_group;" ::: "memory")
#define CP_WAIT0()  asm volatile("cp.async.wait_group 0;" ::: "memory")

// -------------------- device scratch --------------------
__device__ float g_qf[TT*BB*EE];
__device__ float g_vf[TT*BB*EE];
__device__ float g_ctx[TT*BB*EE];
__device__ float g_invnorm[TT*BB];
__device__ int   g_hash[BB*RR*HH*TT];
__device__ int   g_perm[BB*RR*HH*TT];
__device__ int   g_inv [BB*RR*HH*TT];
__device__ float g_o[RR*BB*HH*TT*DD];
__device__ float g_z[RR*BB*HH*TT];

// ==================== exact-fp32 SGEMM (f32x2 + cp.async B): out = A @ W + bias ====================
#define KS 16
#define NST (KTOT/KS)   // 64

__global__ void __launch_bounds__(256, 2) sgemm_kernel(
    const float* __restrict__ A0, const float* __restrict__ W0,
    const float* __restrict__ b0, float* __restrict__ o0,
    const float* __restrict__ A1, const float* __restrict__ W1,
    const float* __restrict__ b1, float* __restrict__ o1)
{
    const float* A    = blockIdx.z ? A1 : A0;
    const float* W    = blockIdx.z ? W1 : W0;
    const float* bias = blockIdx.z ? b1 : b0;
    float*       out  = blockIdx.z ? o1 : o0;

    __shared__ __align__(16) float As[2][KS][132];
    __shared__ __align__(16) float Bs[2][KS][128];
    __shared__ float bsm[128];

    const int tid = threadIdx.x;
    const int bm = blockIdx.y * 128;
    const int bn = blockIdx.x * 128;
    const int tx = tid & 15;
    const int ty = tid >> 4;

    if (tid < 128) bsm[tid] = bias[bn + tid];

    const int arow = tid >> 2;
    const int akq  = tid & 3;
    const int bkr = tid >> 5;
    const int bn4 = tid & 31;

    const float* Ap0 = A + (size_t)(bm + arow) * KTOT + akq * 4;
    const float* Ap1 = A + (size_t)(bm + 64 + arow) * KTOT + akq * 4;
    const float* Wp0 = W + (size_t)bkr * NTOT + bn + bn4 * 4;
    const float* Wp1 = W + (size_t)(8 + bkr) * NTOT + bn + bn4 * 4;

    const uint32_t bs_a0 = smem_u32(&Bs[0][bkr][bn4*4]);
    const uint32_t bs_a1 = smem_u32(&Bs[0][8+bkr][bn4*4]);
    const uint32_t bs_b0 = smem_u32(&Bs[1][bkr][bn4*4]);
    const uint32_t bs_b1 = smem_u32(&Bs[1][8+bkr][bn4*4]);

    float4 pa0, pa1;
    u64 acc2[4][8];
    #pragma unroll
    for (int i = 0; i < 4; i++)
        #pragma unroll
        for (int j = 0; j < 8; j++) acc2[i][j] = 0ull;

    pa0 = *(const float4*)(Ap0);
    pa1 = *(const float4*)(Ap1);
    cp_async16(bs_a0, Wp0);
    cp_async16(bs_a1, Wp1);
    CP_COMMIT();
    {
        const int kb = akq * 4;
        As[0][kb+0][arow]    = pa0.x; As[0][kb+1][arow]    = pa0.y;
        As[0][kb+2][arow]    = pa0.z; As[0][kb+3][arow]    = pa0.w;
        As[0][kb+0][64+arow] = pa1.x; As[0][kb+1][64+arow] = pa1.y;
        As[0][kb+2][64+arow] = pa1.z; As[0][kb+3][64+arow] = pa1.w;
    }
    CP_WAIT0();
    __syncthreads();

    for (int s = 0; s < NST; s++) {
        const int buf = s & 1;
        if (s + 1 < NST) {
            const size_t ko = (size_t)(s + 1) * KS;
            pa0 = *(const float4*)(Ap0 + ko);
            pa1 = *(const float4*)(Ap1 + ko);
            cp_async16(buf ? bs_a0 : bs_b0, Wp0 + ko * NTOT);
            cp_async16(buf ? bs_a1 : bs_b1, Wp1 + ko * NTOT);
            CP_COMMIT();
        }
        #pragma unroll
        for (int k = 0; k < KS; k++) {
            ulonglong2 a0 = *(const ulonglong2*)&As[buf][k][ty*4];
            ulonglong2 a1 = *(const ulonglong2*)&As[buf][k][64 + ty*4];
            float4 bv0 = *(const float4*)&Bs[buf][k][tx*4];
            float4 bv1 = *(const float4*)&Bs[buf][k][64 + tx*4];
            u64 ap[4] = {a0.x, a0.y, a1.x, a1.y};
            u64 bs2[8];
            SPLAT2(bs2[0], __float_as_uint(bv0.x));
            SPLAT2(bs2[1], __float_as_uint(bv0.y));
            SPLAT2(bs2[2], __float_as_uint(bv0.z));
            SPLAT2(bs2[3], __float_as_uint(bv0.w));
            SPLAT2(bs2[4], __float_as_uint(bv1.x));
            SPLAT2(bs2[5], __float_as_uint(bv1.y));
            SPLAT2(bs2[6], __float_as_uint(bv1.z));
            SPLAT2(bs2[7], __float_as_uint(bv1.w));
            #pragma unroll
            for (int i = 0; i < 4; i++)
                #pragma unroll
                for (int j = 0; j < 8; j++)
                    FMA2(acc2[i][j], ap[i], bs2[j]);
        }
        if (s + 1 < NST) {
            const int nb = buf ^ 1;
            __syncthreads();
            const int kb = akq * 4;
            As[nb][kb+0][arow]    = pa0.x; As[nb][kb+1][arow]    = pa0.y;
            As[nb][kb+2][arow]    = pa0.z; As[nb][kb+3][arow]    = pa0.w;
            As[nb][kb+0][64+arow] = pa1.x; As[nb][kb+1][64+arow] = pa1.y;
            As[nb][kb+2][64+arow] = pa1.z; As[nb][kb+3][64+arow] = pa1.w;
            CP_WAIT0();
            __syncthreads();
        }
    }

    #pragma unroll
    for (int i2 = 0; i2 < 4; i2++) {
        const int mrow = bm + ((i2 < 2) ? (ty*4 + i2*2) : (64 + ty*4 + (i2-2)*2));
        const int n0 = tx*4, n1 = 64 + tx*4;
        float* r0 = out + (size_t)mrow * NTOT + bn;
        float* r1 = out + (size_t)(mrow+1) * NTOT + bn;
        float4 lo0, lo1, hi0, hi1;
        lo0.x = lo_f(acc2[i2][0]) + bsm[n0+0]; hi0.x = hi_f(acc2[i2][0]) + bsm[n0+0];
        lo0.y = lo_f(acc2[i2][1]) + bsm[n0+1]; hi0.y = hi_f(acc2[i2][1]) + bsm[n0+1];
        lo0.z = lo_f(acc2[i2][2]) + bsm[n0+2]; hi0.z = hi_f(acc2[i2][2]) + bsm[n0+2];
        lo0.w = lo_f(acc2[i2][3]) + bsm[n0+3]; hi0.w = hi_f(acc2[i2][3]) + bsm[n0+3];
        lo1.x = lo_f(acc2[i2][4]) + bsm[n1+0]; hi1.x = hi_f(acc2[i2][4]) + bsm[n1+0];
        lo1.y = lo_f(acc2[i2][5]) + bsm[n1+1]; hi1.y = hi_f(acc2[i2][5]) + bsm[n1+1];
        lo1.z = lo_f(acc2[i2][6]) + bsm[n1+2]; hi1.z = hi_f(acc2[i2][6]) + bsm[n1+2];
        lo1.w = lo_f(acc2[i2][7]) + bsm[n1+3]; hi1.w = hi_f(acc2[i2][7]) + bsm[n1+3];
        *(float4*)(r0 + n0) = lo0;
        *(float4*)(r0 + n1) = lo1;
        *(float4*)(r1 + n0) = hi0;
        *(float4*)(r1 + n1) = hi1;
    }
}

// ==================== norm + hash (register-serial dots, no reductions) ====================
__global__ void __launch_bounds__(256) norm_hash_kernel(const float* __restrict__ hw)
{
    __shared__ float w_s[RR*HH*DD*4];   // 8192 floats = 32 KB
    int tid = threadIdx.x, lane = tid & 31, wp = tid >> 5;
    int tb0 = blockIdx.x * 16;

    #pragma unroll
    for (int i = 0; i < 8; i++)
        ((float4*)w_s)[tid + i*256] = ((const float4*)hw)[tid + i*256];

    #pragma unroll
    for (int rr = 0; rr < 2; rr++) {
        int tb = tb0 + wp*2 + rr;
        const float4* row = (const float4*)(g_qf + (size_t)tb*EE);
        float ss = 0.f;
        #pragma unroll
        for (int i = 0; i < 8; i++) {
            float4 v = row[lane + i*32];
            ss += v.x*v.x + v.y*v.y + v.z*v.z + v.w*v.w;
        }
        #pragma unroll
        for (int o = 16; o; o >>= 1) ss += __shfl_xor_sync(0xffffffffu, ss, o);
        if (lane == 0) g_invnorm[tb] = 1.0f / sqrtf(ss);
    }
    __syncthreads();

    int row = tid & 15, rh = tid >> 4;
    int r = rh >> 3, h = rh & 7;
    int tb = tb0 + row;
    int t = tb >> 1, b = tb & 1;
    const float4* x = (const float4*)(g_qf + (size_t)tb*EE + h*DD);
    const float4* wseg = (const float4*)(w_s + (r*HH + h)*DD*4);

    float l0 = 0.f, l1 = 0.f, l2 = 0.f, l3 = 0.f;
    #pragma unroll 8
    for (int d4 = 0; d4 < 32; d4++) {
        float4 xv = x[d4];
        float4 w0 = wseg[d4*4+0], w1 = wseg[d4*4+1];
        float4 w2 = wseg[d4*4+2], w3 = wseg[d4*4+3];
        l0 += xv.x*w0.x + xv.y*w1.x + xv.z*w2.x + xv.w*w3.x;
        l1 += xv.x*w0.y + xv.y*w1.y + xv.z*w2.y + xv.w*w3.y;
        l2 += xv.x*w0.z + xv.y*w1.z + xv.z*w2.z + xv.w*w3.z;
        l3 += xv.x*w0.w + xv.y*w1.w + xv.z*w2.w + xv.w*w3.w;
    }
    float best = l0; int bi = 0;
    if (l1 > best) { best = l1; bi = 1; }
    if (l2 > best) { best = l2; bi = 2; }
    if (l3 > best) { best = l3; bi = 3; }
    if (-l0 > best) { best = -l0; bi = 4; }
    if (-l1 > best) { best = -l1; bi = 5; }
    if (-l2 > best) { best = -l2; bi = 6; }
    if (-l3 > best) { best = -l3; bi = 7; }
    g_hash[((b*RR + r)*HH + h)*TT + t] = bi;
}

// ==================== stable counting sort (warp-parallel scan) ====================
__global__ void __launch_bounds__(256) sort_kernel()
{
    int brh = blockIdx.x;
    const int* hs = g_hash + brh*TT;
    int* pp = g_perm + brh*TT;
    int* iv = g_inv  + brh*TT;
    __shared__ int hist[256][9];     // padded: conflict-free column scans
    __shared__ int btot[8], binbase[8];
    int tid = threadIdx.x, lane = tid & 31, wp = tid >> 5;
    int base = tid*8;
    int myh[8];
    int loc[8] = {0,0,0,0,0,0,0,0};
    #pragma unroll
    for (int i = 0; i < 8; i++) { int v = hs[base+i]; myh[i] = v; loc[v]++; }
    #pragma unroll
    for (int v = 0; v < 8; v++) hist[tid][v] = loc[v];
    __syncthreads();
    {
        int carry = 0;
        #pragma unroll
        for (int c = 0; c < 8; c++) {
            int v = hist[c*32 + lane][wp];
            int s = v;
            #pragma unroll
            for (int o = 1; o < 32; o <<= 1) {
                int n = __shfl_up_sync(0xffffffffu, s, o);
                if (lane >= o) s += n;
            }
            hist[c*32 + lane][wp] = carry + s - v;   // exclusive
            carry += __shfl_sync(0xffffffffu, s, 31);
        }
        if (lane == 0) btot[wp] = carry;
    }
    __syncthreads();
    if (tid == 0) {
        int s = 0;
        #pragma unroll
        for (int v = 0; v < 8; v++) { binbase[v] = s; s += btot[v]; }
    }
    __syncthreads();
    int off[8];
    #pragma unroll
    for (int v = 0; v < 8; v++) off[v] = binbase[v] + hist[tid][v];
    #pragma unroll
    for (int i = 0; i < 8; i++) {
        int v = myh[i];
        int pos = off[v]++;
        pp[pos] = base + i;
        iv[base + i] = pos;
    }
}

// ==================== chunked LSH attention (raw-k cp.async, k-side norm) ====================
#define QS 132
#define PS 100
#define ATTN_SMEM_BYTES (128*QS*4)   // 67584

__global__ void __launch_bounds__(256, 3) attn_kernel()
{
    extern __shared__ float sm[];
    float* k_s = sm;                 // 128 x 132 (raw qf rows)
    float* p_s = sm;                 // aliases k_s after QK: 64 x 100
    __shared__ int s_kid[128], s_kh[128], s_ck[256];
    __shared__ float s_kinv[128];
    __shared__ u64 s_vp[128];
    __shared__ u64 s_qp[128];

    int bid = blockIdx.x;
    int cg = bid & 31;
    int h = (bid >> 5) & 7;
    int r = (bid >> 8) & 1;
    int b = bid >> 9;
    int brh = (b*RR + r)*HH + h;
    const int* pp = g_perm + brh*TT;
    int tid = threadIdx.x, lane = tid & 31, wp = tid >> 5;

    if (tid < 128) {
        int wc = (cg*2 + (tid >> 5) + CC - 1) & (CC - 1);
        int kid = pp[wc*32 + (tid & 31)];
        s_kid[tid] = kid;
        s_kh[tid] = g_hash[brh*TT + kid];
        s_kinv[tid] = g_invnorm[kid*BB + b];
        s_ck[tid*2+0] = g_inv[((b*RR+0)*HH+h)*TT + kid] >> 5;
        s_ck[tid*2+1] = g_inv[((b*RR+1)*HH+h)*TT + kid] >> 5;
        size_t rowoff = (size_t)kid*(BB*EE) + (size_t)b*EE + h*DD;
        s_vp[tid] = (u64)(g_vf + rowoff);
        s_qp[tid] = (u64)(g_qf + rowoff);
    }
    __syncthreads();

    {
        uint32_t ksb = smem_u32(k_s);
        for (int idx = tid; idx < 128*32; idx += 256) {
            int j = idx >> 5, d4 = idx & 31;
            cp_async16(ksb + (uint32_t)(j*QS + d4*4)*4u, (const float*)s_qp[j] + d4*4);
        }
        CP_COMMIT();
        CP_WAIT0();
    }
    __syncthreads();

    const int kb = (wp >> 2) * 32;
    const int l0 = wp * 8;

    u64 acc2[8][3];
    #pragma unroll
    for (int i = 0; i < 8; i++) { acc2[i][0]=0ull; acc2[i][1]=0ull; acc2[i][2]=0ull; }
    {
        const float* kp0 = k_s + (kb + lane)*QS;
        const float* kp1 = kp0 + 32*QS;
        const float* kp2 = kp0 + 64*QS;
        const float* qp  = k_s + (32 + l0)*QS;
        #pragma unroll 2
        for (int d4 = 0; d4 < 32; d4++) {
            ulonglong2 k0 = *(const ulonglong2*)(kp0 + d4*4);
            ulonglong2 k1 = *(const ulonglong2*)(kp1 + d4*4);
            ulonglong2 k2 = *(const ulonglong2*)(kp2 + d4*4);
            #pragma unroll
            for (int i = 0; i < 8; i++) {
                ulonglong2 qv = *(const ulonglong2*)(qp + i*QS + d4*4);
                FMA2(acc2[i][0], qv.x, k0.x); FMA2(acc2[i][0], qv.y, k0.y);
                FMA2(acc2[i][1], qv.x, k1.x); FMA2(acc2[i][1], qv.y, k1.y);
                FMA2(acc2[i][2], qv.x, k2.x); FMA2(acc2[i][2], qv.y, k2.y);
            }
        }
    }
    float acc[8][3];
    #pragma unroll
    for (int i = 0; i < 8; i++)
        #pragma unroll
        for (int mi = 0; mi < 3; mi++)
            acc[i][mi] = lo_f(acc2[i][mi]) + hi_f(acc2[i][mi]);

    const float scale = 0.08838834764831845f;  // 128^-0.5
    {
        int khv[3], kidv[3], ck0[3], ck1[3];
        float kf[3];
        #pragma unroll
        for (int mi = 0; mi < 3; mi++) {
            int m = kb + mi*32 + lane;
            khv[mi] = s_kh[m]; kidv[mi] = s_kid[m];
            ck0[mi] = s_ck[m*2+0]; ck1[mi] = s_ck[m*2+1];
            kf[mi] = scale * s_kinv[m];
        }
        #pragma unroll
        for (int i = 0; i < 8; i++) {
            int row = 32 + l0 + i;
            int qh = s_kh[row], qid = s_kid[row];
            int cq0 = s_ck[row*2], cq1 = s_ck[row*2+1];
            #pragma unroll
            for (int mi = 0; mi < 3; mi++) {
                float s = acc[i][mi] * kf[mi];
                if (qh != khv[mi])   s -= 1.0e16f;
                if (qid == kidv[mi]) s -= 1.0e8f;
                int d0 = (ck0[mi] - cq0) & (CC-1);
                int d1 = (ck1[mi] - cq1) & (CC-1);
                int dup = ((d0 <= 1) | (d0 == CC-1)) + ((d1 <= 1) | (d1 == CC-1));
                if (dup == 2) s -= 0.6931471805599453f;
                acc[i][mi] = s;
            }
            float mx = fmaxf(acc[i][0], fmaxf(acc[i][1], acc[i][2]));
            #pragma unroll
            for (int o = 16; o; o >>= 1) mx = fmaxf(mx, __shfl_xor_sync(0xffffffffu, mx, o));
            float p0 = __expf(acc[i][0]-mx), p1 = __expf(acc[i][1]-mx), p2 = __expf(acc[i][2]-mx);
            float sum = p0 + p1 + p2;
            #pragma unroll
            for (int o = 16; o; o >>= 1) sum += __shfl_xor_sync(0xffffffffu, sum, o);
            float rinv = 1.0f / sum;
            acc[i][0] = p0*rinv; acc[i][1] = p1*rinv; acc[i][2] = p2*rinv;
            if (lane == 0) g_z[((r*BB + b)*HH + h)*TT + qid] = __logf(sum) + mx;
        }
    }
    __syncthreads();

    #pragma unroll
    for (int i = 0; i < 8; i++) {
        float* pr = p_s + (l0 + i)*PS;
        pr[lane]      = acc[i][0];
        pr[32 + lane] = acc[i][1];
        pr[64 + lane] = acc[i][2];
    }
    __syncthreads();

    {
        const int dbase = lane*4;
        u64 o01[8], o23[8];
        #pragma unroll
        for (int i = 0; i < 8; i++) { o01[i]=0ull; o23[i]=0ull; }
        #pragma unroll 2
        for (int m4 = 0; m4 < 24; m4++) {
            int m0 = kb + m4*4;
            ulonglong2 v0 = *(const ulonglong2*)((const float*)s_vp[m0+0] + dbase);
            ulonglong2 v1 = *(const ulonglong2*)((const float*)s_vp[m0+1] + dbase);
            ulonglong2 v2 = *(const ulonglong2*)((const float*)s_vp[m0+2] + dbase);
            ulonglong2 v3 = *(const ulonglong2*)((const float*)s_vp[m0+3] + dbase);
            #pragma unroll
            for (int i = 0; i < 8; i++) {
                float4 pv = *(const float4*)&p_s[(l0+i)*PS + m4*4];
                u64 s0, s1, s2, s3;
                SPLAT2(s0, __float_as_uint(pv.x));
                SPLAT2(s1, __float_as_uint(pv.y));
                SPLAT2(s2, __float_as_uint(pv.z));
                SPLAT2(s3, __float_as_uint(pv.w));
                FMA2(o01[i], s0, v0.x); FMA2(o23[i], s0, v0.y);
                FMA2(o01[i], s1, v1.x); FMA2(o23[i], s1, v1.y);
                FMA2(o01[i], s2, v2.x); FMA2(o23[i], s2, v2.y);
                FMA2(o01[i], s3, v3.x); FMA2(o23[i], s3, v3.y);
            }
        }
        #pragma unroll
        for (int i = 0; i < 8; i++) {
            int qid = s_kid[32 + l0 + i];
            float* op = g_o + ((size_t)((r*BB + b)*HH + h)*TT + qid)*DD + dbase;
            *(float4*)op = make_float4(lo_f(o01[i]), hi_f(o01[i]), lo_f(o23[i]), hi_f(o23[i]));
        }
    }
}

// ==================== round combination (float4) ====================
__global__ void __launch_bounds__(256) combine_kernel()
{
    int idx = blockIdx.x*256 + threadIdx.x;   // over B*H*T*D/4 = 2^20
    int d4 = idx & 31;
    int t = (idx >> 5) & 2047;
    int h = (idx >> 16) & 7;
    int b = idx >> 19;
    int zi = (b*HH + h)*TT + t;
    float z0 = g_z[zi];
    float z1 = g_z[BB*HH*TT + zi];
    float mz = fmaxf(z0, z1);
    float e0 = __expf(z0 - mz), e1 = __expf(z1 - mz);
    float winv = 1.0f / (e0 + e1);
    float w0 = e0 * winv, w1 = e1 * winv;
    const float4* o4 = (const float4*)g_o;
    int oi = ((b*HH + h)*TT + t)*32 + d4;
    float4 v0 = o4[oi];
    float4 v1 = o4[BB*HH*TT*32 + oi];
    float4 out;
    out.x = w0*v0.x + w1*v1.x;
    out.y = w0*v0.y + w1*v1.y;
    out.z = w0*v0.z + w1*v1.z;
    out.w = w0*v0.w + w1*v1.w;
    ((float4*)g_ctx)[(t*BB + b)*256 + h*32 + d4] = out;
}

// ==================== launch ====================
extern "C" void kernel_launch(void* const* d_in, const int* in_sizes, int n_in,
                              void* d_out, int out_size)
{
    const float* query = (const float*)d_in[0];
    const float* value = (const float*)d_in[2];
    const float* Wq = (const float*)d_in[3];
    const float* bq = (const float*)d_in[4];
    const float* Wv = (const float*)d_in[5];
    const float* bv = (const float*)d_in[6];
    const float* Wo = (const float*)d_in[7];
    const float* bo = (const float*)d_in[8];
    const float* hw = (const float*)d_in[9];

    float* qf;  cudaGetSymbolAddress((void**)&qf,  g_qf);
    float* vf;  cudaGetSymbolAddress((void**)&vf,  g_vf);
    float* ctx; cudaGetSymbolAddress((void**)&ctx, g_ctx);

    cudaFuncSetAttribute(attn_kernel, cudaFuncAttributeMaxDynamicSharedMemorySize, ATTN_SMEM_BYTES);

    dim3 gqv(NTOT/128, (TT*BB)/128, 2);   // fused Wq + Wv projections
    dim3 go (NTOT/128, (TT*BB)/128, 1);   // Wo projection

    sgemm_kernel<<<gqv, 256>>>(query, Wq, bq, qf, value, Wv, bv, vf);
    norm_hash_kernel<<<(TT*BB)/16, 256>>>(hw);
    sort_kernel<<<BB*RR*HH, 256>>>();
    attn_kernel<<<BB*RR*HH*32, 256, ATTN_SMEM_BYTES>>>();
    combine_kernel<<<(BB*HH*TT*DD/4)/256, 256>>>();
    sgemm_kernel<<<go, 256>>>(ctx, Wo, bo, (float*)d_out,
                              ctx, Wo, bo, (float*)d_out);
}

// round 16
// speedup vs baseline: 1.1004x; 1.0640x over previous
#include <cuda_runtime.h>
#include <math.h>
#include <stdint.h>

// Problem constants
#define TT 2048
#define BB 2
#define EE 1024
#define HH 8
#define DD 128
#define RR 2
#define CHUNKC 32
#define CC (TT/CHUNKC)   // 64
#define KTOT 1024
#define NTOT 1024

typedef unsigned long long u64;

// packed f32x2 helpers (sm_100+ PTX; ptxas never auto-fuses these)
#define FMA2(acc, x, y) \
    asm("fma.rn.f32x2 %0, %1, %2, %0;" : "+l"(acc) : "l"(x), "l"(y))
#define SPLAT2(d, s) \
    asm("mov.b64 %0, {%1, %1};" : "=l"(d) : "r"(s))

__device__ __forceinline__ float lo_f(u64 v) { return __uint_as_float((uint32_t)v); }
__device__ __forceinline__ float hi_f(u64 v) { return __uint_as_float((uint32_t)(v >> 32)); }

__device__ __forceinline__ uint32_t smem_u32(const void* p) {
    uint32_t a;
    asm("{ .reg .u64 t; cvta.to.shared.u64 t, %1; cvt.u32.u64 %0, t; }" : "=r"(a) : "l"(p));
    return a;
}
__device__ __forceinline__ void cp_async16(uint32_t smem_addr, const void* gptr) {
    asm volatile("cp.async.ca.shared.global [%0], [%1], 16;" :: "r"(smem_addr), "l"(gptr));
}
#define CP_COMMIT() asm volatile("cp.async.commit_group;" ::: "memory")
#define CP_WAIT0()  asm volatile("cp.async.wait_group 0;" ::: "memory")

// -------------------- device scratch --------------------
__device__ float g_qf[TT*BB*EE];
__device__ float g_vf[TT*BB*EE];
__device__ float g_ctx[TT*BB*EE];
__device__ float g_invnorm[TT*BB];
__device__ int   g_hash[BB*RR*HH*TT];
__device__ int   g_perm[BB*RR*HH*TT];
__device__ int   g_inv [BB*RR*HH*TT];
__device__ float g_o[RR*BB*HH*TT*DD];
__device__ float g_z[RR*BB*HH*TT];

// ==================== exact-fp32 SGEMM (f32x2 + cp.async B): out = A @ W + bias ====================
// CTA tile 64(M) x 128(N), 128 threads, per-thread 8x8 (4 m-pairs x 8 n) — same inner
// math/order as the 128x128 version, so outputs are bitwise identical. The smaller
// work quantum cuts per-SM integer imbalance: 1024 CTAs/launch -> max/avg = 7/6.92.
#define KS 16
#define NST (KTOT/KS)   // 64

__global__ void __launch_bounds__(128, 4) sgemm_kernel(
    const float* __restrict__ A0, const float* __restrict__ W0,
    const float* __restrict__ b0, float* __restrict__ o0,
    const float* __restrict__ A1, const float* __restrict__ W1,
    const float* __restrict__ b1, float* __restrict__ o1)
{
    const float* A    = blockIdx.z ? A1 : A0;
    const float* W    = blockIdx.z ? W1 : W0;
    const float* bias = blockIdx.z ? b1 : b0;
    float*       out  = blockIdx.z ? o1 : o0;

    __shared__ __align__(16) float As[2][KS][68];
    __shared__ __align__(16) float Bs[2][KS][128];
    __shared__ float bsm[128];

    const int tid = threadIdx.x;
    const int bm = blockIdx.y * 64;
    const int bn = blockIdx.x * 128;
    const int tx = tid & 15;
    const int ty = tid >> 4;           // 0..7

    bsm[tid] = bias[bn + tid];

    const int arow = tid >> 1;         // 0..63
    const int akh  = (tid & 1) * 8;    // this thread's 8 consecutive k

    const float* Ap = A + (size_t)(bm + arow) * KTOT + akh;

    const int bkr = tid >> 5;          // 0..3 (k-row base; +i*4 per cp)
    const int bn4 = tid & 31;
    const float* Wp = W + (size_t)bkr * NTOT + bn + bn4 * 4;

    const uint32_t bsm0 = smem_u32(&Bs[0][bkr][bn4*4]);
    const uint32_t bsm1 = smem_u32(&Bs[1][bkr][bn4*4]);
    // Bs row stride = 128 floats = 512 B; cp i targets row bkr + i*4 -> +i*2048 B

    float4 pa0, pa1;
    u64 acc2[4][8];
    #pragma unroll
    for (int i = 0; i < 4; i++)
        #pragma unroll
        for (int j = 0; j < 8; j++) acc2[i][j] = 0ull;

    // stage 0
    pa0 = *(const float4*)(Ap);
    pa1 = *(const float4*)(Ap + 4);
    #pragma unroll
    for (int i = 0; i < 4; i++)
        cp_async16(bsm0 + (uint32_t)i*2048u, Wp + (size_t)i*4*NTOT);
    CP_COMMIT();
    {
        As[0][akh+0][arow] = pa0.x; As[0][akh+1][arow] = pa0.y;
        As[0][akh+2][arow] = pa0.z; As[0][akh+3][arow] = pa0.w;
        As[0][akh+4][arow] = pa1.x; As[0][akh+5][arow] = pa1.y;
        As[0][akh+6][arow] = pa1.z; As[0][akh+7][arow] = pa1.w;
    }
    CP_WAIT0();
    __syncthreads();

    for (int s = 0; s < NST; s++) {
        const int buf = s & 1;
        if (s + 1 < NST) {
            const size_t ko = (size_t)(s + 1) * KS;
            pa0 = *(const float4*)(Ap + ko);
            pa1 = *(const float4*)(Ap + ko + 4);
            const uint32_t bdst = buf ? bsm0 : bsm1;
            #pragma unroll
            for (int i = 0; i < 4; i++)
                cp_async16(bdst + (uint32_t)i*2048u, Wp + (ko + (size_t)i*4)*NTOT);
            CP_COMMIT();
        }
        #pragma unroll
        for (int k = 0; k < KS; k++) {
            ulonglong2 a0 = *(const ulonglong2*)&As[buf][k][ty*4];
            ulonglong2 a1 = *(const ulonglong2*)&As[buf][k][32 + ty*4];
            float4 bv0 = *(const float4*)&Bs[buf][k][tx*4];
            float4 bv1 = *(const float4*)&Bs[buf][k][64 + tx*4];
            u64 ap[4] = {a0.x, a0.y, a1.x, a1.y};
            u64 bs2[8];
            SPLAT2(bs2[0], __float_as_uint(bv0.x));
            SPLAT2(bs2[1], __float_as_uint(bv0.y));
            SPLAT2(bs2[2], __float_as_uint(bv0.z));
            SPLAT2(bs2[3], __float_as_uint(bv0.w));
            SPLAT2(bs2[4], __float_as_uint(bv1.x));
            SPLAT2(bs2[5], __float_as_uint(bv1.y));
            SPLAT2(bs2[6], __float_as_uint(bv1.z));
            SPLAT2(bs2[7], __float_as_uint(bv1.w));
            #pragma unroll
            for (int i = 0; i < 4; i++)
                #pragma unroll
                for (int j = 0; j < 8; j++)
                    FMA2(acc2[i][j], ap[i], bs2[j]);
        }
        if (s + 1 < NST) {
            const int nb = buf ^ 1;
            __syncthreads();
            As[nb][akh+0][arow] = pa0.x; As[nb][akh+1][arow] = pa0.y;
            As[nb][akh+2][arow] = pa0.z; As[nb][akh+3][arow] = pa0.w;
            As[nb][akh+4][arow] = pa1.x; As[nb][akh+5][arow] = pa1.y;
            As[nb][akh+6][arow] = pa1.z; As[nb][akh+7][arow] = pa1.w;
            CP_WAIT0();
            __syncthreads();
        }
    }

    #pragma unroll
    for (int i2 = 0; i2 < 4; i2++) {
        const int mrow = bm + ((i2 < 2) ? (ty*4 + i2*2) : (32 + ty*4 + (i2-2)*2));
        const int n0 = tx*4, n1 = 64 + tx*4;
        float* r0 = out + (size_t)mrow * NTOT + bn;
        float* r1 = out + (size_t)(mrow+1) * NTOT + bn;
        float4 lo0, lo1, hi0, hi1;
        lo0.x = lo_f(acc2[i2][0]) + bsm[n0+0]; hi0.x = hi_f(acc2[i2][0]) + bsm[n0+0];
        lo0.y = lo_f(acc2[i2][1]) + bsm[n0+1]; hi0.y = hi_f(acc2[i2][1]) + bsm[n0+1];
        lo0.z = lo_f(acc2[i2][2]) + bsm[n0+2]; hi0.z = hi_f(acc2[i2][2]) + bsm[n0+2];
        lo0.w = lo_f(acc2[i2][3]) + bsm[n0+3]; hi0.w = hi_f(acc2[i2][3]) + bsm[n0+3];
        lo1.x = lo_f(acc2[i2][4]) + bsm[n1+0]; hi1.x = hi_f(acc2[i2][4]) + bsm[n1+0];
        lo1.y = lo_f(acc2[i2][5]) + bsm[n1+1]; hi1.y = hi_f(acc2[i2][5]) + bsm[n1+1];
        lo1.z = lo_f(acc2[i2][6]) + bsm[n1+2]; hi1.z = hi_f(acc2[i2][6]) + bsm[n1+2];
        lo1.w = lo_f(acc2[i2][7]) + bsm[n1+3]; hi1.w = hi_f(acc2[i2][7]) + bsm[n1+3];
        *(float4*)(r0 + n0) = lo0;
        *(float4*)(r0 + n1) = lo1;
        *(float4*)(r1 + n0) = hi0;
        *(float4*)(r1 + n1) = hi1;
    }
}

// ==================== norm + hash (register-serial dots, no reductions) ====================
__global__ void __launch_bounds__(256) norm_hash_kernel(const float* __restrict__ hw)
{
    __shared__ float w_s[RR*HH*DD*4];   // 8192 floats = 32 KB
    int tid = threadIdx.x, lane = tid & 31, wp = tid >> 5;
    int tb0 = blockIdx.x * 16;

    #pragma unroll
    for (int i = 0; i < 8; i++)
        ((float4*)w_s)[tid + i*256] = ((const float4*)hw)[tid + i*256];

    #pragma unroll
    for (int rr = 0; rr < 2; rr++) {
        int tb = tb0 + wp*2 + rr;
        const float4* row = (const float4*)(g_qf + (size_t)tb*EE);
        float ss = 0.f;
        #pragma unroll
        for (int i = 0; i < 8; i++) {
            float4 v = row[lane + i*32];
            ss += v.x*v.x + v.y*v.y + v.z*v.z + v.w*v.w;
        }
        #pragma unroll
        for (int o = 16; o; o >>= 1) ss += __shfl_xor_sync(0xffffffffu, ss, o);
        if (lane == 0) g_invnorm[tb] = 1.0f / sqrtf(ss);
    }
    __syncthreads();

    int row = tid & 15, rh = tid >> 4;
    int r = rh >> 3, h = rh & 7;
    int tb = tb0 + row;
    int t = tb >> 1, b = tb & 1;
    const float4* x = (const float4*)(g_qf + (size_t)tb*EE + h*DD);
    const float4* wseg = (const float4*)(w_s + (r*HH + h)*DD*4);

    float l0 = 0.f, l1 = 0.f, l2 = 0.f, l3 = 0.f;
    #pragma unroll 8
    for (int d4 = 0; d4 < 32; d4++) {
        float4 xv = x[d4];
        float4 w0 = wseg[d4*4+0], w1 = wseg[d4*4+1];
        float4 w2 = wseg[d4*4+2], w3 = wseg[d4*4+3];
        l0 += xv.x*w0.x + xv.y*w1.x + xv.z*w2.x + xv.w*w3.x;
        l1 += xv.x*w0.y + xv.y*w1.y + xv.z*w2.y + xv.w*w3.y;
        l2 += xv.x*w0.z + xv.y*w1.z + xv.z*w2.z + xv.w*w3.z;
        l3 += xv.x*w0.w + xv.y*w1.w + xv.z*w2.w + xv.w*w3.w;
    }
    float best = l0; int bi = 0;
    if (l1 > best) { best = l1; bi = 1; }
    if (l2 > best) { best = l2; bi = 2; }
    if (l3 > best) { best = l3; bi = 3; }
    if (-l0 > best) { best = -l0; bi = 4; }
    if (-l1 > best) { best = -l1; bi = 5; }
    if (-l2 > best) { best = -l2; bi = 6; }
    if (-l3 > best) { best = -l3; bi = 7; }
    g_hash[((b*RR + r)*HH + h)*TT + t] = bi;
}

// ==================== stable counting sort (warp-parallel scan) ====================
__global__ void __launch_bounds__(256) sort_kernel()
{
    int brh = blockIdx.x;
    const int* hs = g_hash + brh*TT;
    int* pp = g_perm + brh*TT;
    int* iv = g_inv  + brh*TT;
    __shared__ int hist[256][9];     // padded: conflict-free column scans
    __shared__ int btot[8], binbase[8];
    int tid = threadIdx.x, lane = tid & 31, wp = tid >> 5;
    int base = tid*8;
    int myh[8];
    int loc[8] = {0,0,0,0,0,0,0,0};
    #pragma unroll
    for (int i = 0; i < 8; i++) { int v = hs[base+i]; myh[i] = v; loc[v]++; }
    #pragma unroll
    for (int v = 0; v < 8; v++) hist[tid][v] = loc[v];
    __syncthreads();
    {
        int carry = 0;
        #pragma unroll
        for (int c = 0; c < 8; c++) {
            int v = hist[c*32 + lane][wp];
            int s = v;
            #pragma unroll
            for (int o = 1; o < 32; o <<= 1) {
                int n = __shfl_up_sync(0xffffffffu, s, o);
                if (lane >= o) s += n;
            }
            hist[c*32 + lane][wp] = carry + s - v;   // exclusive
            carry += __shfl_sync(0xffffffffu, s, 31);
        }
        if (lane == 0) btot[wp] = carry;
    }
    __syncthreads();
    if (tid == 0) {
        int s = 0;
        #pragma unroll
        for (int v = 0; v < 8; v++) { binbase[v] = s; s += btot[v]; }
    }
    __syncthreads();
    int off[8];
    #pragma unroll
    for (int v = 0; v < 8; v++) off[v] = binbase[v] + hist[tid][v];
    #pragma unroll
    for (int i = 0; i < 8; i++) {
        int v = myh[i];
        int pos = off[v]++;
        pp[pos] = base + i;
        iv[base + i] = pos;
    }
}

// ==================== chunked LSH attention (raw-k cp.async, k-side norm) ====================
#define QS 132
#define PS 100
#define ATTN_SMEM_BYTES (128*QS*4)   // 67584

__global__ void __launch_bounds__(256, 3) attn_kernel()
{
    extern __shared__ float sm[];
    float* k_s = sm;                 // 128 x 132 (raw qf rows)
    float* p_s = sm;                 // aliases k_s after QK: 64 x 100
    __shared__ int s_kid[128], s_kh[128], s_ck[256];
    __shared__ float s_kinv[128];
    __shared__ u64 s_vp[128];
    __shared__ u64 s_qp[128];

    int bid = blockIdx.x;
    int cg = bid & 31;
    int h = (bid >> 5) & 7;
    int r = (bid >> 8) & 1;
    int b = bid >> 9;
    int brh = (b*RR + r)*HH + h;
    const int* pp = g_perm + brh*TT;
    int tid = threadIdx.x, lane = tid & 31, wp = tid >> 5;

    if (tid < 128) {
        int wc = (cg*2 + (tid >> 5) + CC - 1) & (CC - 1);
        int kid = pp[wc*32 + (tid & 31)];
        s_kid[tid] = kid;
        s_kh[tid] = g_hash[brh*TT + kid];
        s_kinv[tid] = g_invnorm[kid*BB + b];
        s_ck[tid*2+0] = g_inv[((b*RR+0)*HH+h)*TT + kid] >> 5;
        s_ck[tid*2+1] = g_inv[((b*RR+1)*HH+h)*TT + kid] >> 5;
        size_t rowoff = (size_t)kid*(BB*EE) + (size_t)b*EE + h*DD;
        s_vp[tid] = (u64)(g_vf + rowoff);
        s_qp[tid] = (u64)(g_qf + rowoff);
    }
    __syncthreads();

    {
        uint32_t ksb = smem_u32(k_s);
        for (int idx = tid; idx < 128*32; idx += 256) {
            int j = idx >> 5, d4 = idx & 31;
            cp_async16(ksb + (uint32_t)(j*QS + d4*4)*4u, (const float*)s_qp[j] + d4*4);
        }
        CP_COMMIT();
        CP_WAIT0();
    }
    __syncthreads();

    const int kb = (wp >> 2) * 32;
    const int l0 = wp * 8;

    u64 acc2[8][3];
    #pragma unroll
    for (int i = 0; i < 8; i++) { acc2[i][0]=0ull; acc2[i][1]=0ull; acc2[i][2]=0ull; }
    {
        const float* kp0 = k_s + (kb + lane)*QS;
        const float* kp1 = kp0 + 32*QS;
        const float* kp2 = kp0 + 64*QS;
        const float* qp  = k_s + (32 + l0)*QS;
        #pragma unroll 2
        for (int d4 = 0; d4 < 32; d4++) {
            ulonglong2 k0 = *(const ulonglong2*)(kp0 + d4*4);
            ulonglong2 k1 = *(const ulonglong2*)(kp1 + d4*4);
            ulonglong2 k2 = *(const ulonglong2*)(kp2 + d4*4);
            #pragma unroll
            for (int i = 0; i < 8; i++) {
                ulonglong2 qv = *(const ulonglong2*)(qp + i*QS + d4*4);
                FMA2(acc2[i][0], qv.x, k0.x); FMA2(acc2[i][0], qv.y, k0.y);
                FMA2(acc2[i][1], qv.x, k1.x); FMA2(acc2[i][1], qv.y, k1.y);
                FMA2(acc2[i][2], qv.x, k2.x); FMA2(acc2[i][2], qv.y, k2.y);
            }
        }
    }
    float acc[8][3];
    #pragma unroll
    for (int i = 0; i < 8; i++)
        #pragma unroll
        for (int mi = 0; mi < 3; mi++)
            acc[i][mi] = lo_f(acc2[i][mi]) + hi_f(acc2[i][mi]);

    const float scale = 0.08838834764831845f;  // 128^-0.5
    {
        int khv[3], kidv[3], ck0[3], ck1[3];
        float kf[3];
        #pragma unroll
        for (int mi = 0; mi < 3; mi++) {
            int m = kb + mi*32 + lane;
            khv[mi] = s_kh[m]; kidv[mi] = s_kid[m];
            ck0[mi] = s_ck[m*2+0]; ck1[mi] = s_ck[m*2+1];
            kf[mi] = scale * s_kinv[m];
        }
        #pragma unroll
        for (int i = 0; i < 8; i++) {
            int row = 32 + l0 + i;
            int qh = s_kh[row], qid = s_kid[row];
            int cq0 = s_ck[row*2], cq1 = s_ck[row*2+1];
            #pragma unroll
            for (int mi = 0; mi < 3; mi++) {
                float s = acc[i][mi] * kf[mi];
                if (qh != khv[mi])   s -= 1.0e16f;
                if (qid == kidv[mi]) s -= 1.0e8f;
                int d0 = (ck0[mi] - cq0) & (CC-1);
                int d1 = (ck1[mi] - cq1) & (CC-1);
                int dup = ((d0 <= 1) | (d0 == CC-1)) + ((d1 <= 1) | (d1 == CC-1));
                if (dup == 2) s -= 0.6931471805599453f;
                acc[i][mi] = s;
            }
            float mx = fmaxf(acc[i][0], fmaxf(acc[i][1], acc[i][2]));
            #pragma unroll
            for (int o = 16; o; o >>= 1) mx = fmaxf(mx, __shfl_xor_sync(0xffffffffu, mx, o));
            float p0 = __expf(acc[i][0]-mx), p1 = __expf(acc[i][1]-mx), p2 = __expf(acc[i][2]-mx);
            float sum = p0 + p1 + p2;
            #pragma unroll
            for (int o = 16; o; o >>= 1) sum += __shfl_xor_sync(0xffffffffu, sum, o);
            float rinv = 1.0f / sum;
            acc[i][0] = p0*rinv; acc[i][1] = p1*rinv; acc[i][2] = p2*rinv;
            if (lane == 0) g_z[((r*BB + b)*HH + h)*TT + qid] = __logf(sum) + mx;
        }
    }
    __syncthreads();

    #pragma unroll
    for (int i = 0; i < 8; i++) {
        float* pr = p_s + (l0 + i)*PS;
        pr[lane]      = acc[i][0];
        pr[32 + lane] = acc[i][1];
        pr[64 + lane] = acc[i][2];
    }
    __syncthreads();

    {
        const int dbase = lane*4;
        u64 o01[8], o23[8];
        #pragma unroll
        for (int i = 0; i < 8; i++) { o01[i]=0ull; o23[i]=0ull; }
        #pragma unroll 2
        for (int m4 = 0; m4 < 24; m4++) {
            int m0 = kb + m4*4;
            ulonglong2 v0 = *(const ulonglong2*)((const float*)s_vp[m0+0] + dbase);
            ulonglong2 v1 = *(const ulonglong2*)((const float*)s_vp[m0+1] + dbase);
            ulonglong2 v2 = *(const ulonglong2*)((const float*)s_vp[m0+2] + dbase);
            ulonglong2 v3 = *(const ulonglong2*)((const float*)s_vp[m0+3] + dbase);
            #pragma unroll
            for (int i = 0; i < 8; i++) {
                float4 pv = *(const float4*)&p_s[(l0+i)*PS + m4*4];
                u64 s0, s1, s2, s3;
                SPLAT2(s0, __float_as_uint(pv.x));
                SPLAT2(s1, __float_as_uint(pv.y));
                SPLAT2(s2, __float_as_uint(pv.z));
                SPLAT2(s3, __float_as_uint(pv.w));
                FMA2(o01[i], s0, v0.x); FMA2(o23[i], s0, v0.y);
                FMA2(o01[i], s1, v1.x); FMA2(o23[i], s1, v1.y);
                FMA2(o01[i], s2, v2.x); FMA2(o23[i], s2, v2.y);
                FMA2(o01[i], s3, v3.x); FMA2(o23[i], s3, v3.y);
            }
        }
        #pragma unroll
        for (int i = 0; i < 8; i++) {
            int qid = s_kid[32 + l0 + i];
            float* op = g_o + ((size_t)((r*BB + b)*HH + h)*TT + qid)*DD + dbase;
            *(float4*)op = make_float4(lo_f(o01[i]), hi_f(o01[i]), lo_f(o23[i]), hi_f(o23[i]));
        }
    }
}

// ==================== round combination (float4) ====================
__global__ void __launch_bounds__(256) combine_kernel()
{
    int idx = blockIdx.x*256 + threadIdx.x;   // over B*H*T*D/4 = 2^20
    int d4 = idx & 31;
    int t = (idx >> 5) & 2047;
    int h = (idx >> 16) & 7;
    int b = idx >> 19;
    int zi = (b*HH + h)*TT + t;
    float z0 = g_z[zi];
    float z1 = g_z[BB*HH*TT + zi];
    float mz = fmaxf(z0, z1);
    float e0 = __expf(z0 - mz), e1 = __expf(z1 - mz);
    float winv = 1.0f / (e0 + e1);
    float w0 = e0 * winv, w1 = e1 * winv;
    const float4* o4 = (const float4*)g_o;
    int oi = ((b*HH + h)*TT + t)*32 + d4;
    float4 v0 = o4[oi];
    float4 v1 = o4[BB*HH*TT*32 + oi];
    float4 out;
    out.x = w0*v0.x + w1*v1.x;
    out.y = w0*v0.y + w1*v1.y;
    out.z = w0*v0.z + w1*v1.z;
    out.w = w0*v0.w + w1*v1.w;
    ((float4*)g_ctx)[(t*BB + b)*256 + h*32 + d4] = out;
}

// ==================== launch ====================
extern "C" void kernel_launch(void* const* d_in, const int* in_sizes, int n_in,
                              void* d_out, int out_size)
{
    const float* query = (const float*)d_in[0];
    const float* value = (const float*)d_in[2];
    const float* Wq = (const float*)d_in[3];
    const float* bq = (const float*)d_in[4];
    const float* Wv = (const float*)d_in[5];
    const float* bv = (const float*)d_in[6];
    const float* Wo = (const float*)d_in[7];
    const float* bo = (const float*)d_in[8];
    const float* hw = (const float*)d_in[9];

    float* qf;  cudaGetSymbolAddress((void**)&qf,  g_qf);
    float* vf;  cudaGetSymbolAddress((void**)&vf,  g_vf);
    float* ctx; cudaGetSymbolAddress((void**)&ctx, g_ctx);

    cudaFuncSetAttribute(attn_kernel, cudaFuncAttributeMaxDynamicSharedMemorySize, ATTN_SMEM_BYTES);

    dim3 gqv(NTOT/128, (TT*BB)/64, 2);   // fused Wq + Wv projections (1024 CTAs)
    dim3 go (NTOT/128, (TT*BB)/64, 1);   // Wo projection (512 CTAs)

    sgemm_kernel<<<gqv, 128>>>(query, Wq, bq, qf, value, Wv, bv, vf);
    norm_hash_kernel<<<(TT*BB)/16, 256>>>(hw);
    sort_kernel<<<BB*RR*HH, 256>>>();
    attn_kernel<<<BB*RR*HH*32, 256, ATTN_SMEM_BYTES>>>();
    combine_kernel<<<(BB*HH*TT*DD/4)/256, 256>>>();
    sgemm_kernel<<<go, 128>>>(ctx, Wo, bo, (float*)d_out,
                              ctx, Wo, bo, (float*)d_out);
}

// round 17
// speedup vs baseline: 1.1350x; 1.0314x over previous
#include <cuda_runtime.h>
#include <math.h>
#include <stdint.h>

// Problem constants
#define TT 2048
#define BB 2
#define EE 1024
#define HH 8
#define DD 128
#define RR 2
#define CHUNKC 32
#define CC (TT/CHUNKC)   // 64
#define KTOT 1024
#define NTOT 1024

typedef unsigned long long u64;

// packed f32x2 helpers (sm_100+ PTX; ptxas never auto-fuses these)
#define FMA2(acc, x, y) \
    asm("fma.rn.f32x2 %0, %1, %2, %0;" : "+l"(acc) : "l"(x), "l"(y))
#define SPLAT2(d, s) \
    asm("mov.b64 %0, {%1, %1};" : "=l"(d) : "r"(s))

__device__ __forceinline__ float lo_f(u64 v) { return __uint_as_float((uint32_t)v); }
__device__ __forceinline__ float hi_f(u64 v) { return __uint_as_float((uint32_t)(v >> 32)); }

__device__ __forceinline__ uint32_t smem_u32(const void* p) {
    uint32_t a;
    asm("{ .reg .u64 t; cvta.to.shared.u64 t, %1; cvt.u32.u64 %0, t; }" : "=r"(a) : "l"(p));
    return a;
}
__device__ __forceinline__ void cp_async16(uint32_t smem_addr, const void* gptr) {
    asm volatile("cp.async.ca.shared.global [%0], [%1], 16;" :: "r"(smem_addr), "l"(gptr));
}
#define CP_COMMIT() asm volatile("cp.async.commit_group;" ::: "memory")
#define CP_WAIT0()  asm volatile("cp.async.wait_group 0;" ::: "memory")

// -------------------- device scratch --------------------
__device__ float g_qf[TT*BB*EE];      // Wq output; later reused as Wo partial 0
__device__ float g_vf[TT*BB*EE];      // Wv output; later reused as Wo partial 1
__device__ float g_ctx[TT*BB*EE];
__device__ float g_invnorm[TT*BB];
__device__ int   g_hash[BB*RR*HH*TT];
__device__ int   g_perm[BB*RR*HH*TT];
__device__ int   g_inv [BB*RR*HH*TT];
__device__ float g_o[RR*BB*HH*TT*DD];
__device__ float g_z[RR*BB*HH*TT];

// ==================== exact-fp32 SGEMM (f32x2 + cp.async B): out = A @ W + bias ====================
// CTA tile 64(M) x 128(N), 128 threads, per-thread 8x8 (4 m-pairs x 8 n).
#define KS 16
#define NST (KTOT/KS)   // 64

__global__ void __launch_bounds__(128, 4) sgemm_kernel(
    const float* __restrict__ A0, const float* __restrict__ W0,
    const float* __restrict__ b0, float* __restrict__ o0,
    const float* __restrict__ A1, const float* __restrict__ W1,
    const float* __restrict__ b1, float* __restrict__ o1)
{
    const float* A    = blockIdx.z ? A1 : A0;
    const float* W    = blockIdx.z ? W1 : W0;
    const float* bias = blockIdx.z ? b1 : b0;
    float*       out  = blockIdx.z ? o1 : o0;

    __shared__ __align__(16) float As[2][KS][68];
    __shared__ __align__(16) float Bs[2][KS][128];
    __shared__ float bsm[128];

    const int tid = threadIdx.x;
    const int bm = blockIdx.y * 64;
    const int bn = blockIdx.x * 128;
    const int tx = tid & 15;
    const int ty = tid >> 4;           // 0..7

    bsm[tid] = bias[bn + tid];

    const int arow = tid >> 1;         // 0..63
    const int akh  = (tid & 1) * 8;    // this thread's 8 consecutive k

    const float* Ap = A + (size_t)(bm + arow) * KTOT + akh;

    const int bkr = tid >> 5;          // 0..3
    const int bn4 = tid & 31;
    const float* Wp = W + (size_t)bkr * NTOT + bn + bn4 * 4;

    const uint32_t bsm0 = smem_u32(&Bs[0][bkr][bn4*4]);
    const uint32_t bsm1 = smem_u32(&Bs[1][bkr][bn4*4]);

    float4 pa0, pa1;
    u64 acc2[4][8];
    #pragma unroll
    for (int i = 0; i < 4; i++)
        #pragma unroll
        for (int j = 0; j < 8; j++) acc2[i][j] = 0ull;

    pa0 = *(const float4*)(Ap);
    pa1 = *(const float4*)(Ap + 4);
    #pragma unroll
    for (int i = 0; i < 4; i++)
        cp_async16(bsm0 + (uint32_t)i*2048u, Wp + (size_t)i*4*NTOT);
    CP_COMMIT();
    {
        As[0][akh+0][arow] = pa0.x; As[0][akh+1][arow] = pa0.y;
        As[0][akh+2][arow] = pa0.z; As[0][akh+3][arow] = pa0.w;
        As[0][akh+4][arow] = pa1.x; As[0][akh+5][arow] = pa1.y;
        As[0][akh+6][arow] = pa1.z; As[0][akh+7][arow] = pa1.w;
    }
    CP_WAIT0();
    __syncthreads();

    for (int s = 0; s < NST; s++) {
        const int buf = s & 1;
        if (s + 1 < NST) {
            const size_t ko = (size_t)(s + 1) * KS;
            pa0 = *(const float4*)(Ap + ko);
            pa1 = *(const float4*)(Ap + ko + 4);
            const uint32_t bdst = buf ? bsm0 : bsm1;
            #pragma unroll
            for (int i = 0; i < 4; i++)
                cp_async16(bdst + (uint32_t)i*2048u, Wp + (ko + (size_t)i*4)*NTOT);
            CP_COMMIT();
        }
        #pragma unroll
        for (int k = 0; k < KS; k++) {
            ulonglong2 a0 = *(const ulonglong2*)&As[buf][k][ty*4];
            ulonglong2 a1 = *(const ulonglong2*)&As[buf][k][32 + ty*4];
            float4 bv0 = *(const float4*)&Bs[buf][k][tx*4];
            float4 bv1 = *(const float4*)&Bs[buf][k][64 + tx*4];
            u64 ap[4] = {a0.x, a0.y, a1.x, a1.y};
            u64 bs2[8];
            SPLAT2(bs2[0], __float_as_uint(bv0.x));
            SPLAT2(bs2[1], __float_as_uint(bv0.y));
            SPLAT2(bs2[2], __float_as_uint(bv0.z));
            SPLAT2(bs2[3], __float_as_uint(bv0.w));
            SPLAT2(bs2[4], __float_as_uint(bv1.x));
            SPLAT2(bs2[5], __float_as_uint(bv1.y));
            SPLAT2(bs2[6], __float_as_uint(bv1.z));
            SPLAT2(bs2[7], __float_as_uint(bv1.w));
            #pragma unroll
            for (int i = 0; i < 4; i++)
                #pragma unroll
                for (int j = 0; j < 8; j++)
                    FMA2(acc2[i][j], ap[i], bs2[j]);
        }
        if (s + 1 < NST) {
            const int nb = buf ^ 1;
            __syncthreads();
            As[nb][akh+0][arow] = pa0.x; As[nb][akh+1][arow] = pa0.y;
            As[nb][akh+2][arow] = pa0.z; As[nb][akh+3][arow] = pa0.w;
            As[nb][akh+4][arow] = pa1.x; As[nb][akh+5][arow] = pa1.y;
            As[nb][akh+6][arow] = pa1.z; As[nb][akh+7][arow] = pa1.w;
            CP_WAIT0();
            __syncthreads();
        }
    }

    #pragma unroll
    for (int i2 = 0; i2 < 4; i2++) {
        const int mrow = bm + ((i2 < 2) ? (ty*4 + i2*2) : (32 + ty*4 + (i2-2)*2));
        const int n0 = tx*4, n1 = 64 + tx*4;
        float* r0 = out + (size_t)mrow * NTOT + bn;
        float* r1 = out + (size_t)(mrow+1) * NTOT + bn;
        float4 lo0, lo1, hi0, hi1;
        lo0.x = lo_f(acc2[i2][0]) + bsm[n0+0]; hi0.x = hi_f(acc2[i2][0]) + bsm[n0+0];
        lo0.y = lo_f(acc2[i2][1]) + bsm[n0+1]; hi0.y = hi_f(acc2[i2][1]) + bsm[n0+1];
        lo0.z = lo_f(acc2[i2][2]) + bsm[n0+2]; hi0.z = hi_f(acc2[i2][2]) + bsm[n0+2];
        lo0.w = lo_f(acc2[i2][3]) + bsm[n0+3]; hi0.w = hi_f(acc2[i2][3]) + bsm[n0+3];
        lo1.x = lo_f(acc2[i2][4]) + bsm[n1+0]; hi1.x = hi_f(acc2[i2][4]) + bsm[n1+0];
        lo1.y = lo_f(acc2[i2][5]) + bsm[n1+1]; hi1.y = hi_f(acc2[i2][5]) + bsm[n1+1];
        lo1.z = lo_f(acc2[i2][6]) + bsm[n1+2]; hi1.z = hi_f(acc2[i2][6]) + bsm[n1+2];
        lo1.w = lo_f(acc2[i2][7]) + bsm[n1+3]; hi1.w = hi_f(acc2[i2][7]) + bsm[n1+3];
        *(float4*)(r0 + n0) = lo0;
        *(float4*)(r0 + n1) = lo1;
        *(float4*)(r1 + n0) = hi0;
        *(float4*)(r1 + n1) = hi1;
    }
}

// ==================== K-split SGEMM half (no bias): out = A[:, z*512:+512] @ W[z*512:+512, :] ====
#define KH 512
#define NSTH (KH/KS)   // 32

__global__ void __launch_bounds__(128, 4) sgemm_half_kernel(
    const float* __restrict__ Afull, const float* __restrict__ Wfull,
    float* __restrict__ out0, float* __restrict__ out1)
{
    const size_t koff = (size_t)blockIdx.z * KH;
    const float* A = Afull + koff;                 // column offset into K
    const float* W = Wfull + koff * NTOT;          // row offset into K
    float* out = blockIdx.z ? out1 : out0;

    __shared__ __align__(16) float As[2][KS][68];
    __shared__ __align__(16) float Bs[2][KS][128];

    const int tid = threadIdx.x;
    const int bm = blockIdx.y * 64;
    const int bn = blockIdx.x * 128;
    const int tx = tid & 15;
    const int ty = tid >> 4;

    const int arow = tid >> 1;
    const int akh  = (tid & 1) * 8;
    const float* Ap = A + (size_t)(bm + arow) * KTOT + akh;

    const int bkr = tid >> 5;
    const int bn4 = tid & 31;
    const float* Wp = W + (size_t)bkr * NTOT + bn + bn4 * 4;

    const uint32_t bsm0 = smem_u32(&Bs[0][bkr][bn4*4]);
    const uint32_t bsm1 = smem_u32(&Bs[1][bkr][bn4*4]);

    float4 pa0, pa1;
    u64 acc2[4][8];
    #pragma unroll
    for (int i = 0; i < 4; i++)
        #pragma unroll
        for (int j = 0; j < 8; j++) acc2[i][j] = 0ull;

    pa0 = *(const float4*)(Ap);
    pa1 = *(const float4*)(Ap + 4);
    #pragma unroll
    for (int i = 0; i < 4; i++)
        cp_async16(bsm0 + (uint32_t)i*2048u, Wp + (size_t)i*4*NTOT);
    CP_COMMIT();
    {
        As[0][akh+0][arow] = pa0.x; As[0][akh+1][arow] = pa0.y;
        As[0][akh+2][arow] = pa0.z; As[0][akh+3][arow] = pa0.w;
        As[0][akh+4][arow] = pa1.x; As[0][akh+5][arow] = pa1.y;
        As[0][akh+6][arow] = pa1.z; As[0][akh+7][arow] = pa1.w;
    }
    CP_WAIT0();
    __syncthreads();

    for (int s = 0; s < NSTH; s++) {
        const int buf = s & 1;
        if (s + 1 < NSTH) {
            const size_t ko = (size_t)(s + 1) * KS;
            pa0 = *(const float4*)(Ap + ko);
            pa1 = *(const float4*)(Ap + ko + 4);
            const uint32_t bdst = buf ? bsm0 : bsm1;
            #pragma unroll
            for (int i = 0; i < 4; i++)
                cp_async16(bdst + (uint32_t)i*2048u, Wp + (ko + (size_t)i*4)*NTOT);
            CP_COMMIT();
        }
        #pragma unroll
        for (int k = 0; k < KS; k++) {
            ulonglong2 a0 = *(const ulonglong2*)&As[buf][k][ty*4];
            ulonglong2 a1 = *(const ulonglong2*)&As[buf][k][32 + ty*4];
            float4 bv0 = *(const float4*)&Bs[buf][k][tx*4];
            float4 bv1 = *(const float4*)&Bs[buf][k][64 + tx*4];
            u64 ap[4] = {a0.x, a0.y, a1.x, a1.y};
            u64 bs2[8];
            SPLAT2(bs2[0], __float_as_uint(bv0.x));
            SPLAT2(bs2[1], __float_as_uint(bv0.y));
            SPLAT2(bs2[2], __float_as_uint(bv0.z));
            SPLAT2(bs2[3], __float_as_uint(bv0.w));
            SPLAT2(bs2[4], __float_as_uint(bv1.x));
            SPLAT2(bs2[5], __float_as_uint(bv1.y));
            SPLAT2(bs2[6], __float_as_uint(bv1.z));
            SPLAT2(bs2[7], __float_as_uint(bv1.w));
            #pragma unroll
            for (int i = 0; i < 4; i++)
                #pragma unroll
                for (int j = 0; j < 8; j++)
                    FMA2(acc2[i][j], ap[i], bs2[j]);
        }
        if (s + 1 < NSTH) {
            const int nb = buf ^ 1;
            __syncthreads();
            As[nb][akh+0][arow] = pa0.x; As[nb][akh+1][arow] = pa0.y;
            As[nb][akh+2][arow] = pa0.z; As[nb][akh+3][arow] = pa0.w;
            As[nb][akh+4][arow] = pa1.x; As[nb][akh+5][arow] = pa1.y;
            As[nb][akh+6][arow] = pa1.z; As[nb][akh+7][arow] = pa1.w;
            CP_WAIT0();
            __syncthreads();
        }
    }

    #pragma unroll
    for (int i2 = 0; i2 < 4; i2++) {
        const int mrow = bm + ((i2 < 2) ? (ty*4 + i2*2) : (32 + ty*4 + (i2-2)*2));
        const int n0 = tx*4, n1 = 64 + tx*4;
        float* r0 = out + (size_t)mrow * NTOT + bn;
        float* r1 = out + (size_t)(mrow+1) * NTOT + bn;
        *(float4*)(r0 + n0) = make_float4(lo_f(acc2[i2][0]), lo_f(acc2[i2][1]),
                                          lo_f(acc2[i2][2]), lo_f(acc2[i2][3]));
        *(float4*)(r0 + n1) = make_float4(lo_f(acc2[i2][4]), lo_f(acc2[i2][5]),
                                          lo_f(acc2[i2][6]), lo_f(acc2[i2][7]));
        *(float4*)(r1 + n0) = make_float4(hi_f(acc2[i2][0]), hi_f(acc2[i2][1]),
                                          hi_f(acc2[i2][2]), hi_f(acc2[i2][3]));
        *(float4*)(r1 + n1) = make_float4(hi_f(acc2[i2][4]), hi_f(acc2[i2][5]),
                                          hi_f(acc2[i2][6]), hi_f(acc2[i2][7]));
    }
}

// ==================== add partials + bias (float4) ====================
__global__ void __launch_bounds__(256) add_bias_kernel(
    const float* __restrict__ p0, const float* __restrict__ p1,
    const float* __restrict__ bias, float* __restrict__ out)
{
    int idx = blockIdx.x*256 + threadIdx.x;     // over M*N/4 = 2^20
    int n4 = idx & 255;
    float4 a = ((const float4*)p0)[idx];
    float4 b = ((const float4*)p1)[idx];
    float4 c = ((const float4*)bias)[n4];
    float4 o;
    o.x = a.x + b.x + c.x;
    o.y = a.y + b.y + c.y;
    o.z = a.z + b.z + c.z;
    o.w = a.w + b.w + c.w;
    ((float4*)out)[idx] = o;
}

// ==================== norm + hash (register-serial dots, no reductions) ====================
__global__ void __launch_bounds__(256) norm_hash_kernel(const float* __restrict__ hw)
{
    __shared__ float w_s[RR*HH*DD*4];   // 8192 floats = 32 KB
    int tid = threadIdx.x, lane = tid & 31, wp = tid >> 5;
    int tb0 = blockIdx.x * 16;

    #pragma unroll
    for (int i = 0; i < 8; i++)
        ((float4*)w_s)[tid + i*256] = ((const float4*)hw)[tid + i*256];

    #pragma unroll
    for (int rr = 0; rr < 2; rr++) {
        int tb = tb0 + wp*2 + rr;
        const float4* row = (const float4*)(g_qf + (size_t)tb*EE);
        float ss = 0.f;
        #pragma unroll
        for (int i = 0; i < 8; i++) {
            float4 v = row[lane + i*32];
            ss += v.x*v.x + v.y*v.y + v.z*v.z + v.w*v.w;
        }
        #pragma unroll
        for (int o = 16; o; o >>= 1) ss += __shfl_xor_sync(0xffffffffu, ss, o);
        if (lane == 0) g_invnorm[tb] = 1.0f / sqrtf(ss);
    }
    __syncthreads();

    int row = tid & 15, rh = tid >> 4;
    int r = rh >> 3, h = rh & 7;
    int tb = tb0 + row;
    int t = tb >> 1, b = tb & 1;
    const float4* x = (const float4*)(g_qf + (size_t)tb*EE + h*DD);
    const float4* wseg = (const float4*)(w_s + (r*HH + h)*DD*4);

    float l0 = 0.f, l1 = 0.f, l2 = 0.f, l3 = 0.f;
    #pragma unroll 8
    for (int d4 = 0; d4 < 32; d4++) {
        float4 xv = x[d4];
        float4 w0 = wseg[d4*4+0], w1 = wseg[d4*4+1];
        float4 w2 = wseg[d4*4+2], w3 = wseg[d4*4+3];
        l0 += xv.x*w0.x + xv.y*w1.x + xv.z*w2.x + xv.w*w3.x;
        l1 += xv.x*w0.y + xv.y*w1.y + xv.z*w2.y + xv.w*w3.y;
        l2 += xv.x*w0.z + xv.y*w1.z + xv.z*w2.z + xv.w*w3.z;
        l3 += xv.x*w0.w + xv.y*w1.w + xv.z*w2.w + xv.w*w3.w;
    }
    float best = l0; int bi = 0;
    if (l1 > best) { best = l1; bi = 1; }
    if (l2 > best) { best = l2; bi = 2; }
    if (l3 > best) { best = l3; bi = 3; }
    if (-l0 > best) { best = -l0; bi = 4; }
    if (-l1 > best) { best = -l1; bi = 5; }
    if (-l2 > best) { best = -l2; bi = 6; }
    if (-l3 > best) { best = -l3; bi = 7; }
    g_hash[((b*RR + r)*HH + h)*TT + t] = bi;
}

// ==================== stable counting sort (warp-parallel scan) ====================
__global__ void __launch_bounds__(256) sort_kernel()
{
    int brh = blockIdx.x;
    const int* hs = g_hash + brh*TT;
    int* pp = g_perm + brh*TT;
    int* iv = g_inv  + brh*TT;
    __shared__ int hist[256][9];
    __shared__ int btot[8], binbase[8];
    int tid = threadIdx.x, lane = tid & 31, wp = tid >> 5;
    int base = tid*8;
    int myh[8];
    int loc[8] = {0,0,0,0,0,0,0,0};
    #pragma unroll
    for (int i = 0; i < 8; i++) { int v = hs[base+i]; myh[i] = v; loc[v]++; }
    #pragma unroll
    for (int v = 0; v < 8; v++) hist[tid][v] = loc[v];
    __syncthreads();
    {
        int carry = 0;
        #pragma unroll
        for (int c = 0; c < 8; c++) {
            int v = hist[c*32 + lane][wp];
            int s = v;
            #pragma unroll
            for (int o = 1; o < 32; o <<= 1) {
                int n = __shfl_up_sync(0xffffffffu, s, o);
                if (lane >= o) s += n;
            }
            hist[c*32 + lane][wp] = carry + s - v;
            carry += __shfl_sync(0xffffffffu, s, 31);
        }
        if (lane == 0) btot[wp] = carry;
    }
    __syncthreads();
    if (tid == 0) {
        int s = 0;
        #pragma unroll
        for (int v = 0; v < 8; v++) { binbase[v] = s; s += btot[v]; }
    }
    __syncthreads();
    int off[8];
    #pragma unroll
    for (int v = 0; v < 8; v++) off[v] = binbase[v] + hist[tid][v];
    #pragma unroll
    for (int i = 0; i < 8; i++) {
        int v = myh[i];
        int pos = off[v]++;
        pp[pos] = base + i;
        iv[base + i] = pos;
    }
}

// ==================== chunked LSH attention (raw-k cp.async, k-side norm) ====================
#define QS 132
#define PS 100
#define ATTN_SMEM_BYTES (128*QS*4)   // 67584

__global__ void __launch_bounds__(256, 3) attn_kernel()
{
    extern __shared__ float sm[];
    float* k_s = sm;
    float* p_s = sm;
    __shared__ int s_kid[128], s_kh[128], s_ck[256];
    __shared__ float s_kinv[128];
    __shared__ u64 s_vp[128];
    __shared__ u64 s_qp[128];

    int bid = blockIdx.x;
    int cg = bid & 31;
    int h = (bid >> 5) & 7;
    int r = (bid >> 8) & 1;
    int b = bid >> 9;
    int brh = (b*RR + r)*HH + h;
    const int* pp = g_perm + brh*TT;
    int tid = threadIdx.x, lane = tid & 31, wp = tid >> 5;

    if (tid < 128) {
        int wc = (cg*2 + (tid >> 5) + CC - 1) & (CC - 1);
        int kid = pp[wc*32 + (tid & 31)];
        s_kid[tid] = kid;
        s_kh[tid] = g_hash[brh*TT + kid];
        s_kinv[tid] = g_invnorm[kid*BB + b];
        s_ck[tid*2+0] = g_inv[((b*RR+0)*HH+h)*TT + kid] >> 5;
        s_ck[tid*2+1] = g_inv[((b*RR+1)*HH+h)*TT + kid] >> 5;
        size_t rowoff = (size_t)kid*(BB*EE) + (size_t)b*EE + h*DD;
        s_vp[tid] = (u64)(g_vf + rowoff);
        s_qp[tid] = (u64)(g_qf + rowoff);
    }
    __syncthreads();

    {
        uint32_t ksb = smem_u32(k_s);
        for (int idx = tid; idx < 128*32; idx += 256) {
            int j = idx >> 5, d4 = idx & 31;
            cp_async16(ksb + (uint32_t)(j*QS + d4*4)*4u, (const float*)s_qp[j] + d4*4);
        }
        CP_COMMIT();
        CP_WAIT0();
    }
    __syncthreads();

    const int kb = (wp >> 2) * 32;
    const int l0 = wp * 8;

    u64 acc2[8][3];
    #pragma unroll
    for (int i = 0; i < 8; i++) { acc2[i][0]=0ull; acc2[i][1]=0ull; acc2[i][2]=0ull; }
    {
        const float* kp0 = k_s + (kb + lane)*QS;
        const float* kp1 = kp0 + 32*QS;
        const float* kp2 = kp0 + 64*QS;
        const float* qp  = k_s + (32 + l0)*QS;
        #pragma unroll 2
        for (int d4 = 0; d4 < 32; d4++) {
            ulonglong2 k0 = *(const ulonglong2*)(kp0 + d4*4);
            ulonglong2 k1 = *(const ulonglong2*)(kp1 + d4*4);
            ulonglong2 k2 = *(const ulonglong2*)(kp2 + d4*4);
            #pragma unroll
            for (int i = 0; i < 8; i++) {
                ulonglong2 qv = *(const ulonglong2*)(qp + i*QS + d4*4);
                FMA2(acc2[i][0], qv.x, k0.x); FMA2(acc2[i][0], qv.y, k0.y);
                FMA2(acc2[i][1], qv.x, k1.x); FMA2(acc2[i][1], qv.y, k1.y);
                FMA2(acc2[i][2], qv.x, k2.x); FMA2(acc2[i][2], qv.y, k2.y);
            }
        }
    }
    float acc[8][3];
    #pragma unroll
    for (int i = 0; i < 8; i++)
        #pragma unroll
        for (int mi = 0; mi < 3; mi++)
            acc[i][mi] = lo_f(acc2[i][mi]) + hi_f(acc2[i][mi]);

    const float scale = 0.08838834764831845f;  // 128^-0.5
    {
        int khv[3], kidv[3], ck0[3], ck1[3];
        float kf[3];
        #pragma unroll
        for (int mi = 0; mi < 3; mi++) {
            int m = kb + mi*32 + lane;
            khv[mi] = s_kh[m]; kidv[mi] = s_kid[m];
            ck0[mi] = s_ck[m*2+0]; ck1[mi] = s_ck[m*2+1];
            kf[mi] = scale * s_kinv[m];
        }
        #pragma unroll
        for (int i = 0; i < 8; i++) {
            int row = 32 + l0 + i;
            int qh = s_kh[row], qid = s_kid[row];
            int cq0 = s_ck[row*2], cq1 = s_ck[row*2+1];
            #pragma unroll
            for (int mi = 0; mi < 3; mi++) {
                float s = acc[i][mi] * kf[mi];
                if (qh != khv[mi])   s -= 1.0e16f;
                if (qid == kidv[mi]) s -= 1.0e8f;
                int d0 = (ck0[mi] - cq0) & (CC-1);
                int d1 = (ck1[mi] - cq1) & (CC-1);
                int dup = ((d0 <= 1) | (d0 == CC-1)) + ((d1 <= 1) | (d1 == CC-1));
                if (dup == 2) s -= 0.6931471805599453f;
                acc[i][mi] = s;
            }
            float mx = fmaxf(acc[i][0], fmaxf(acc[i][1], acc[i][2]));
            #pragma unroll
            for (int o = 16; o; o >>= 1) mx = fmaxf(mx, __shfl_xor_sync(0xffffffffu, mx, o));
            float p0 = __expf(acc[i][0]-mx), p1 = __expf(acc[i][1]-mx), p2 = __expf(acc[i][2]-mx);
            float sum = p0 + p1 + p2;
            #pragma unroll
            for (int o = 16; o; o >>= 1) sum += __shfl_xor_sync(0xffffffffu, sum, o);
            float rinv = 1.0f / sum;
            acc[i][0] = p0*rinv; acc[i][1] = p1*rinv; acc[i][2] = p2*rinv;
            if (lane == 0) g_z[((r*BB + b)*HH + h)*TT + qid] = __logf(sum) + mx;
        }
    }
    __syncthreads();

    #pragma unroll
    for (int i = 0; i < 8; i++) {
        float* pr = p_s + (l0 + i)*PS;
        pr[lane]      = acc[i][0];
        pr[32 + lane] = acc[i][1];
        pr[64 + lane] = acc[i][2];
    }
    __syncthreads();

    {
        const int dbase = lane*4;
        u64 o01[8], o23[8];
        #pragma unroll
        for (int i = 0; i < 8; i++) { o01[i]=0ull; o23[i]=0ull; }
        #pragma unroll 2
        for (int m4 = 0; m4 < 24; m4++) {
            int m0 = kb + m4*4;
            ulonglong2 v0 = *(const ulonglong2*)((const float*)s_vp[m0+0] + dbase);
            ulonglong2 v1 = *(const ulonglong2*)((const float*)s_vp[m0+1] + dbase);
            ulonglong2 v2 = *(const ulonglong2*)((const float*)s_vp[m0+2] + dbase);
            ulonglong2 v3 = *(const ulonglong2*)((const float*)s_vp[m0+3] + dbase);
            #pragma unroll
            for (int i = 0; i < 8; i++) {
                float4 pv = *(const float4*)&p_s[(l0+i)*PS + m4*4];
                u64 s0, s1, s2, s3;
                SPLAT2(s0, __float_as_uint(pv.x));
                SPLAT2(s1, __float_as_uint(pv.y));
                SPLAT2(s2, __float_as_uint(pv.z));
                SPLAT2(s3, __float_as_uint(pv.w));
                FMA2(o01[i], s0, v0.x); FMA2(o23[i], s0, v0.y);
                FMA2(o01[i], s1, v1.x); FMA2(o23[i], s1, v1.y);
                FMA2(o01[i], s2, v2.x); FMA2(o23[i], s2, v2.y);
                FMA2(o01[i], s3, v3.x); FMA2(o23[i], s3, v3.y);
            }
        }
        #pragma unroll
        for (int i = 0; i < 8; i++) {
            int qid = s_kid[32 + l0 + i];
            float* op = g_o + ((size_t)((r*BB + b)*HH + h)*TT + qid)*DD + dbase;
            *(float4*)op = make_float4(lo_f(o01[i]), hi_f(o01[i]), lo_f(o23[i]), hi_f(o23[i]));
        }
    }
}

// ==================== round combination (float4) ====================
__global__ void __launch_bounds__(256) combine_kernel()
{
    int idx = blockIdx.x*256 + threadIdx.x;   // over B*H*T*D/4 = 2^20
    int d4 = idx & 31;
    int t = (idx >> 5) & 2047;
    int h = (idx >> 16) & 7;
    int b = idx >> 19;
    int zi = (b*HH + h)*TT + t;
    float z0 = g_z[zi];
    float z1 = g_z[BB*HH*TT + zi];
    float mz = fmaxf(z0, z1);
    float e0 = __expf(z0 - mz), e1 = __expf(z1 - mz);
    float winv = 1.0f / (e0 + e1);
    float w0 = e0 * winv, w1 = e1 * winv;
    const float4* o4 = (const float4*)g_o;
    int oi = ((b*HH + h)*TT + t)*32 + d4;
    float4 v0 = o4[oi];
    float4 v1 = o4[BB*HH*TT*32 + oi];
    float4 out;
    out.x = w0*v0.x + w1*v1.x;
    out.y = w0*v0.y + w1*v1.y;
    out.z = w0*v0.z + w1*v1.z;
    out.w = w0*v0.w + w1*v1.w;
    ((float4*)g_ctx)[(t*BB + b)*256 + h*32 + d4] = out;
}

// ==================== launch ====================
extern "C" void kernel_launch(void* const* d_in, const int* in_sizes, int n_in,
                              void* d_out, int out_size)
{
    const float* query = (const float*)d_in[0];
    const float* value = (const float*)d_in[2];
    const float* Wq = (const float*)d_in[3];
    const float* bq = (const float*)d_in[4];
    const float* Wv = (const float*)d_in[5];
    const float* bv = (const float*)d_in[6];
    const float* Wo = (const float*)d_in[7];
    const float* bo = (const float*)d_in[8];
    const float* hw = (const float*)d_in[9];

    float* qf;  cudaGetSymbolAddress((void**)&qf,  g_qf);
    float* vf;  cudaGetSymbolAddress((void**)&vf,  g_vf);
    float* ctx; cudaGetSymbolAddress((void**)&ctx, g_ctx);

    cudaFuncSetAttribute(attn_kernel, cudaFuncAttributeMaxDynamicSharedMemorySize, ATTN_SMEM_BYTES);

    dim3 gqv(NTOT/128, (TT*BB)/64, 2);   // fused Wq + Wv projections (1024 CTAs)
    dim3 gwo(NTOT/128, (TT*BB)/64, 2);   // Wo K-split (1024 CTAs)

    sgemm_kernel<<<gqv, 128>>>(query, Wq, bq, qf, value, Wv, bv, vf);
    norm_hash_kernel<<<(TT*BB)/16, 256>>>(hw);
    sort_kernel<<<BB*RR*HH, 256>>>();
    attn_kernel<<<BB*RR*HH*32, 256, ATTN_SMEM_BYTES>>>();
    combine_kernel<<<(BB*HH*TT*DD/4)/256, 256>>>();
    // g_qf / g_vf are dead now -> reuse as Wo partial-sum buffers
    sgemm_half_kernel<<<gwo, 128>>>(ctx, Wo, qf, vf);
    add_bias_kernel<<<(TT*BB*NTOT/4)/256, 256>>>(qf, vf, bo, (float*)d_out);
}